// round 6
// baseline (speedup 1.0000x reference)
#include <cuda_runtime.h>
#include <cuda_bf16.h>
#include <cstdint>
#include <math.h>

#define BATCH 16
#define NSEQ  1024
#define NH    8
#define HD    64
#define DM    512

// ---------------- scratch (static device arrays; no allocation) ----------------
#define QKV_ELEMS (BATCH*NH*NSEQ*HD)
__device__ __nv_bfloat16 g_qhi[QKV_ELEMS];
__device__ __nv_bfloat16 g_qlo[QKV_ELEMS];
__device__ __nv_bfloat16 g_khi[QKV_ELEMS];
__device__ __nv_bfloat16 g_klo[QKV_ELEMS];
__device__ __nv_bfloat16 g_vhi[QKV_ELEMS];
__device__ __nv_bfloat16 g_vlo[QKV_ELEMS];
__device__ float g_attn[BATCH*NSEQ*DM];

// =============================================================================
// helpers
// =============================================================================
__device__ __forceinline__ uint32_t smem_u32(const void* p) {
    uint32_t a;
    asm("{ .reg .u64 t; cvta.to.shared.u64 t, %1; cvt.u32.u64 %0, t; }"
        : "=r"(a) : "l"(p));
    return a;
}
__device__ __forceinline__ void ldsm_x4(uint32_t* r, uint32_t addr) {
    asm volatile("ldmatrix.sync.aligned.m8n8.x4.shared.b16 {%0,%1,%2,%3}, [%4];"
        : "=r"(r[0]), "=r"(r[1]), "=r"(r[2]), "=r"(r[3]) : "r"(addr));
}
__device__ __forceinline__ void ldsm_x2(uint32_t* r, uint32_t addr) {
    asm volatile("ldmatrix.sync.aligned.m8n8.x2.shared.b16 {%0,%1}, [%2];"
        : "=r"(r[0]), "=r"(r[1]) : "r"(addr));
}
__device__ __forceinline__ void ldsm_x4t(uint32_t* r, uint32_t addr) {
    asm volatile("ldmatrix.sync.aligned.m8n8.x4.trans.shared.b16 {%0,%1,%2,%3}, [%4];"
        : "=r"(r[0]), "=r"(r[1]), "=r"(r[2]), "=r"(r[3]) : "r"(addr));
}
__device__ __forceinline__ void mma_bf16(float* c, const uint32_t* a,
                                         uint32_t b0, uint32_t b1) {
    asm volatile(
        "mma.sync.aligned.m16n8k16.row.col.f32.bf16.bf16.f32 "
        "{%0,%1,%2,%3}, {%4,%5,%6,%7}, {%8,%9}, {%0,%1,%2,%3};"
        : "+f"(c[0]), "+f"(c[1]), "+f"(c[2]), "+f"(c[3])
        : "r"(a[0]), "r"(a[1]), "r"(a[2]), "r"(a[3]), "r"(b0), "r"(b1));
}
__device__ __forceinline__ void cp16(uint32_t dst, const void* src) {
    asm volatile("cp.async.cg.shared.global [%0], [%1], 16;" :: "r"(dst), "l"(src));
}
#define CP_COMMIT() asm volatile("cp.async.commit_group;" ::: "memory")
#define CP_WAIT0()  asm volatile("cp.async.wait_group 0;" ::: "memory")

__device__ __forceinline__ uint32_t pack_bf16_res(float a, float b, float& ra, float& rb) {
    __nv_bfloat16 ha = __float2bfloat16(a), hb = __float2bfloat16(b);
    ra = a - __bfloat162float(ha);
    rb = b - __bfloat162float(hb);
    __nv_bfloat162 p(ha, hb);
    return *reinterpret_cast<uint32_t*>(&p);
}
__device__ __forceinline__ uint32_t pack_bf16(float a, float b) {
    __nv_bfloat162 p(__float2bfloat16(a), __float2bfloat16(b));
    return *reinterpret_cast<uint32_t*>(&p);
}
__device__ __forceinline__ uint32_t packP(float p) {
    __nv_bfloat16 hi = __float2bfloat16(p);
    __nv_bfloat16 lo = __float2bfloat16(p - __bfloat162float(hi));
    uint16_t hb = *reinterpret_cast<uint16_t*>(&hi);
    uint16_t lb = *reinterpret_cast<uint16_t*>(&lo);
    return (uint32_t)hb | ((uint32_t)lb << 16);
}

// =============================================================================
// Tensor-core (HMMA) GEMM: C[16384,512] = X @ W + bias, bf16 split-3.
// (unchanged from R4 — known good)
// =============================================================================
#define ASTRIDE 40
#define BSTRIDE 136
#define A_BYTES (128*ASTRIDE*2)
#define B_BYTES (32*BSTRIDE*2)
#define OFF_ALO A_BYTES
#define OFF_BHI (2*A_BYTES)
#define OFF_BLO (2*A_BYTES + B_BYTES)
#define GBUF    (2*A_BYTES + 2*B_BYTES)
#define GEMM_SMEM (2*GBUF)

template<int MODE>
__global__ __launch_bounds__(256, 1) void gemm_tc(
    const float* __restrict__ X, const float* __restrict__ W,
    const float* __restrict__ bias, float* __restrict__ out,
    __nv_bfloat16* __restrict__ ohi, __nv_bfloat16* __restrict__ olo)
{
    extern __shared__ char smem[];
    const uint32_t sb = smem_u32(smem);
    const int tid  = threadIdx.x;
    const int wid  = tid >> 5, lane = tid & 31;
    const int wm   = wid >> 2;
    const int wn   = wid & 3;
    const int n0   = blockIdx.x * 128;
    const int m0   = blockIdx.y * 128;

    float acc[4][4][4];
    #pragma unroll
    for (int i = 0; i < 4; i++)
        #pragma unroll
        for (int j = 0; j < 4; j++)
            #pragma unroll
            for (int k = 0; k < 4; k++) acc[i][j][k] = 0.f;

    float4 ra[4], rb[4];

    auto gload = [&](int c) {
        const int k0 = c * 32;
        #pragma unroll
        for (int i = 0; i < 4; i++) {
            int idx = i * 256 + tid;
            int row = idx >> 3, col = (idx & 7) * 4;
            ra[i] = *(const float4*)&X[(size_t)(m0 + row) * 512 + k0 + col];
        }
        #pragma unroll
        for (int i = 0; i < 4; i++) {
            int idx = i * 256 + tid;
            int kk = idx >> 5, col = (idx & 31) * 4;
            rb[i] = *(const float4*)&W[(size_t)(k0 + kk) * 512 + n0 + col];
        }
    };

    auto cstore = [&](int buf) {
        char* bp = smem + buf * GBUF;
        #pragma unroll
        for (int i = 0; i < 4; i++) {
            int idx = i * 256 + tid;
            int row = idx >> 3, col = (idx & 7) * 4;
            float r0, r1, r2, r3;
            uint2 hi, lo;
            hi.x = pack_bf16_res(ra[i].x, ra[i].y, r0, r1);
            hi.y = pack_bf16_res(ra[i].z, ra[i].w, r2, r3);
            lo.x = pack_bf16(r0, r1);
            lo.y = pack_bf16(r2, r3);
            uint32_t off = (uint32_t)(row * ASTRIDE + col) * 2;
            *(uint2*)(bp + off)           = hi;
            *(uint2*)(bp + OFF_ALO + off) = lo;
        }
        #pragma unroll
        for (int i = 0; i < 4; i++) {
            int idx = i * 256 + tid;
            int kk = idx >> 5, col = (idx & 31) * 4;
            float r0, r1, r2, r3;
            uint2 hi, lo;
            hi.x = pack_bf16_res(rb[i].x, rb[i].y, r0, r1);
            hi.y = pack_bf16_res(rb[i].z, rb[i].w, r2, r3);
            lo.x = pack_bf16(r0, r1);
            lo.y = pack_bf16(r2, r3);
            uint32_t off = (uint32_t)(kk * BSTRIDE + col) * 2;
            *(uint2*)(bp + OFF_BHI + off) = hi;
            *(uint2*)(bp + OFF_BLO + off) = lo;
        }
    };

    const uint32_t aLane = (uint32_t)((wm * 64 + (lane & 15)) * ASTRIDE + (lane >> 4) * 8) * 2;
    const uint32_t bLane = (uint32_t)((lane & 15) * BSTRIDE + wn * 32 + (lane >> 4) * 8) * 2;

    auto compute = [&](int buf) {
        const uint32_t base = sb + buf * GBUF;
        #pragma unroll
        for (int ks = 0; ks < 2; ks++) {
            uint32_t ah[4][4], al[4][4], bh[2][4], bl[2][4];
            #pragma unroll
            for (int mt = 0; mt < 4; mt++) {
                uint32_t ad = base + aLane + (uint32_t)(mt * 16 * ASTRIDE + ks * 16) * 2;
                ldsm_x4(ah[mt], ad);
                ldsm_x4(al[mt], ad + OFF_ALO);
            }
            #pragma unroll
            for (int nt = 0; nt < 2; nt++) {
                uint32_t bd = base + OFF_BHI + bLane +
                              (uint32_t)(ks * 16 * BSTRIDE + nt * 16) * 2;
                ldsm_x4t(bh[nt], bd);
                ldsm_x4t(bl[nt], bd + B_BYTES);
            }
            #pragma unroll
            for (int mt = 0; mt < 4; mt++) {
                #pragma unroll
                for (int n8 = 0; n8 < 4; n8++) {
                    const int nt = n8 >> 1, hf = (n8 & 1) * 2;
                    float* c = acc[mt][n8];
                    mma_bf16(c, ah[mt], bh[nt][hf], bh[nt][hf + 1]);
                    mma_bf16(c, ah[mt], bl[nt][hf], bl[nt][hf + 1]);
                    mma_bf16(c, al[mt], bh[nt][hf], bh[nt][hf + 1]);
                }
            }
        }
    };

    gload(0);
    cstore(0);
    __syncthreads();
    for (int c = 0; c < 16; c++) {
        if (c < 15) gload(c + 1);
        compute(c & 1);
        if (c < 15) {
            cstore((c + 1) & 1);
            __syncthreads();
        }
    }

    const int gid = lane >> 2;
    const int cid = (lane & 3) * 2;
    #pragma unroll
    for (int mt = 0; mt < 4; mt++) {
        #pragma unroll
        for (int n8 = 0; n8 < 4; n8++) {
            int row = m0 + wm * 64 + mt * 16 + gid;
            int col = n0 + wn * 32 + n8 * 8 + cid;
            float b0 = __ldg(&bias[col]), b1 = __ldg(&bias[col + 1]);
            float2 v0 = make_float2(acc[mt][n8][0] + b0, acc[mt][n8][1] + b1);
            float2 v1 = make_float2(acc[mt][n8][2] + b0, acc[mt][n8][3] + b1);
            if (MODE == 0) {
                int h = col >> 6, d = col & 63;
                #pragma unroll
                for (int rr = 0; rr < 2; rr++) {
                    int r = row + rr * 8;
                    float2 v = rr ? v1 : v0;
                    int bi = r >> 10, ni = r & 1023;
                    size_t idx = (size_t)(((bi * NH + h) << 10) + ni) * 64 + d;
                    float e0, e1;
                    uint32_t hi = pack_bf16_res(v.x, v.y, e0, e1);
                    uint32_t lo = pack_bf16(e0, e1);
                    *(uint32_t*)&ohi[idx] = hi;
                    *(uint32_t*)&olo[idx] = lo;
                }
            } else {
                *(float2*)&out[(size_t)row * 512 + col]       = v0;
                *(float2*)&out[(size_t)(row + 8) * 512 + col] = v1;
            }
        }
    }
}

// =============================================================================
// Tensor-core fused attention, 256 threads / 8 warps, 16 q-rows per CTA,
// 64-row K/V chunks, ~105KB smem -> 2 CTAs/SM.
// =============================================================================
#define SSTR 1036
#define ATT_KV0  (16*SSTR*4)              // 66304
#define ATT_KVSZ (64*144*2)               // 18432 (hi plane 9216 + lo plane)
#define ATT_LO   9216
#define ATT_Q    (ATT_KV0 + 2*ATT_KVSZ)   // 103168
#define ATT_QLO  2304
#define ATT_SMEM (ATT_Q + 4608)           // 107776

__global__ __launch_bounds__(256, 2) void attn_tc(
    const __nv_bfloat16* __restrict__ qhi, const __nv_bfloat16* __restrict__ qlo,
    const __nv_bfloat16* __restrict__ khi, const __nv_bfloat16* __restrict__ klo,
    const __nv_bfloat16* __restrict__ vhi, const __nv_bfloat16* __restrict__ vlo,
    const float* __restrict__ gw, float* __restrict__ mn,
    float* __restrict__ attnout)
{
    extern __shared__ char smem[];
    float* sS = (float*)smem;
    uint32_t* sSw = (uint32_t*)smem;
    const uint32_t sb = smem_u32(smem);

    const int tid = threadIdx.x, wid = tid >> 5, lane = tid & 31;
    const int q0 = blockIdx.x * 16, hh = blockIdx.y, bb = blockIdx.z;
    const size_t bhBase = (size_t)(bb * NH + hh) * NSEQ;

    // chunk loader: 64 k-rows, hi+lo planes, 4 cp16 per thread
    auto loadChunk = [&](const __nv_bfloat16* hi, const __nv_bfloat16* lo,
                         int kb, int buf) {
        uint32_t dst = sb + ATT_KV0 + buf * ATT_KVSZ;
        const __nv_bfloat16* sh = hi + (bhBase + kb * 64) * 64;
        const __nv_bfloat16* sl = lo + (bhBase + kb * 64) * 64;
        #pragma unroll
        for (int i = 0; i < 2; i++) {
            int idx = i * 256 + tid;
            int row = idx >> 3, col = (idx & 7) * 8;
            uint32_t d = dst + row * 144 + col * 2;
            cp16(d,          sh + row * 64 + col);
            cp16(d + ATT_LO, sl + row * 64 + col);
        }
        CP_COMMIT();
    };

    // ---- issue K chunk 0 immediately ----
    loadChunk(khi, klo, 0, 0);

    // ---- stage Q tile (16x64 hi/lo) ----
    {
        int pos = tid & 127;
        int row = pos >> 3, col = (pos & 7) * 8;
        size_t g = (bhBase + q0 + row) * 64 + col;
        if (tid < 128)
            *(uint4*)(smem + ATT_Q + row * 144 + col * 2)           = *(const uint4*)&qhi[g];
        else
            *(uint4*)(smem + ATT_Q + ATT_QLO + row * 144 + col * 2) = *(const uint4*)&qlo[g];
    }
    __syncthreads();

    // ---- Q fragments (m16 x k64), all warps identical (broadcast) ----
    uint32_t aQh[4][4], aQl[4][4];
    {
        const uint32_t qaddr = sb + ATT_Q +
            ((uint32_t)((lane & 15) * 72) + (lane >> 4) * 8) * 2;
        #pragma unroll
        for (int ks = 0; ks < 4; ks++) {
            ldsm_x4(aQh[ks], qaddr + ks * 32);
            ldsm_x4(aQl[ks], qaddr + ks * 32 + ATT_QLO);
        }
    }

    // ================= QK^T : warp = m16 x n8 slab of the 64-col chunk =========
    for (int kb = 0; kb < 16; kb++) {
        CP_WAIT0();
        __syncthreads();
        if (kb < 15) loadChunk(khi, klo, kb + 1, (kb + 1) & 1);

        const uint32_t baddr = sb + ATT_KV0 + (kb & 1) * ATT_KVSZ +
            ((uint32_t)((wid * 8 + (lane & 7)) * 72) + ((lane >> 3) & 1) * 8) * 2;

        float acc[4] = {0.f, 0.f, 0.f, 0.f};
        #pragma unroll
        for (int ks = 0; ks < 4; ks++) {
            uint32_t bh[2], bl[2];
            ldsm_x2(bh, baddr + ks * 32);
            ldsm_x2(bl, baddr + ks * 32 + ATT_LO);
            mma_bf16(acc, aQh[ks], bh[0], bh[1]);
            mma_bf16(acc, aQh[ks], bl[0], bl[1]);
            mma_bf16(acc, aQl[ks], bh[0], bh[1]);
        }

        int scol = kb * 64 + wid * 8 + (lane & 3) * 2;
        int srow = lane >> 2;
        *(float2*)&sS[srow * SSTR + scol]       = make_float2(acc[0], acc[1]);
        *(float2*)&sS[(srow + 8) * SSTR + scol] = make_float2(acc[2], acc[3]);
    }

    // prefetch V chunk 0 (cp pipeline now empty)
    loadChunk(vhi, vlo, 0, 0);
    __syncthreads();

    // ================= softmax: 2 rows per warp =================
    {
        #pragma unroll
        for (int rr = 0; rr < 2; rr++) {
            int r = wid * 2 + rr;
            float* row = sS + r * SSTR;
            const float* wrow = gw + ((bhBase + q0 + r) << 10);

            float m = -1e30f;
            #pragma unroll
            for (int i = 0; i < 8; i++) {
                int c = (lane + i * 32) * 4;
                float4 f = *(float4*)&row[c];
                float4 w = *(const float4*)&wrow[c];
                f.x = f.x * 0.125f + __logf(fmaxf(w.x, 1e-6f));
                f.y = f.y * 0.125f + __logf(fmaxf(w.y, 1e-6f));
                f.z = f.z * 0.125f + __logf(fmaxf(w.z, 1e-6f));
                f.w = f.w * 0.125f + __logf(fmaxf(w.w, 1e-6f));
                m = fmaxf(m, fmaxf(fmaxf(f.x, f.y), fmaxf(f.z, f.w)));
                *(float4*)&row[c] = f;
            }
            #pragma unroll
            for (int o = 16; o; o >>= 1) m = fmaxf(m, __shfl_xor_sync(0xffffffffu, m, o));

            float sum = 0.f;
            #pragma unroll
            for (int i = 0; i < 8; i++) {
                int c = (lane + i * 32) * 4;
                float4 f = *(float4*)&row[c];
                f.x = __expf(f.x - m); f.y = __expf(f.y - m);
                f.z = __expf(f.z - m); f.w = __expf(f.w - m);
                sum += (f.x + f.y) + (f.z + f.w);
                *(float4*)&row[c] = f;
            }
            #pragma unroll
            for (int o = 16; o; o >>= 1) sum += __shfl_xor_sync(0xffffffffu, sum, o);
            float inv = 1.f / sum;

            float* mrow = mn + ((bhBase + q0 + r) << 10);
            uint32_t* prow = sSw + r * SSTR;
            #pragma unroll
            for (int i = 0; i < 8; i++) {
                int c = (lane + i * 32) * 4;
                float4 f = *(float4*)&row[c];
                f.x *= inv; f.y *= inv; f.z *= inv; f.w *= inv;
                *(float4*)&mrow[c] = f;
                uint4 pk;
                pk.x = packP(f.x); pk.y = packP(f.y);
                pk.z = packP(f.z); pk.w = packP(f.w);
                *(uint4*)&prow[c] = pk;
            }
        }
    }
    __syncthreads();

    // ================= P @ V : warp = m16 x n32 x k16-slice (wn x wk) =========
    const int wn = wid & 1;       // 32-col slab of HD=64
    const int wk = wid >> 1;      // k-slice within each 64-row chunk
    float accO[4][4];
    #pragma unroll
    for (int t = 0; t < 4; t++)
        #pragma unroll
        for (int j = 0; j < 4; j++) accO[t][j] = 0.f;

    const int g  = lane >> 2;
    const int kc = (lane & 3) * 2;
    const int pr0 = g * SSTR;
    const int pr1 = (g + 8) * SSTR;

    for (int kb = 0; kb < 16; kb++) {
        CP_WAIT0();
        __syncthreads();
        if (kb < 15) loadChunk(vhi, vlo, kb + 1, (kb + 1) & 1);

        // P fragment (rows g, g+8; k = wk*16 slice of this chunk)
        int kcol = kb * 64 + wk * 16 + kc;
        uint2 u0 = *(uint2*)&sSw[pr0 + kcol];
        uint2 u1 = *(uint2*)&sSw[pr1 + kcol];
        uint2 u2 = *(uint2*)&sSw[pr0 + kcol + 8];
        uint2 u3 = *(uint2*)&sSw[pr1 + kcol + 8];
        uint32_t ah[4], al[4];
        ah[0] = __byte_perm(u0.x, u0.y, 0x5410);
        al[0] = __byte_perm(u0.x, u0.y, 0x7632);
        ah[1] = __byte_perm(u1.x, u1.y, 0x5410);
        al[1] = __byte_perm(u1.x, u1.y, 0x7632);
        ah[2] = __byte_perm(u2.x, u2.y, 0x5410);
        al[2] = __byte_perm(u2.x, u2.y, 0x7632);
        ah[3] = __byte_perm(u3.x, u3.y, 0x5410);
        al[3] = __byte_perm(u3.x, u3.y, 0x7632);

        const uint32_t vbase = sb + ATT_KV0 + (kb & 1) * ATT_KVSZ;
        #pragma unroll
        for (int ng = 0; ng < 2; ng++) {
            uint32_t vaddr = vbase +
                ((uint32_t)((wk * 16 + (lane & 15)) * 72) +
                 wn * 32 + ng * 16 + (lane >> 4) * 8) * 2;
            uint32_t bh[4], bl[4];
            ldsm_x4t(bh, vaddr);
            ldsm_x4t(bl, vaddr + ATT_LO);
            float* c0 = accO[ng * 2];
            float* c1 = accO[ng * 2 + 1];
            mma_bf16(c0, ah, bh[0], bh[1]);
            mma_bf16(c0, ah, bl[0], bl[1]);
            mma_bf16(c0, al, bh[0], bh[1]);
            mma_bf16(c1, ah, bh[2], bh[3]);
            mma_bf16(c1, ah, bl[2], bl[3]);
            mma_bf16(c1, al, bh[2], bh[3]);
        }
    }
    __syncthreads();   // all P reads done; sS region reusable for reduction

    // ---- k-slice reduction: wk 1..3 write partials into sS area ----
    float* red = (float*)smem;   // 3 slabs of 16x64 fp32 (4KB each)
    if (wk > 0) {
        float* slab = red + (wk - 1) * 1024;
        #pragma unroll
        for (int t = 0; t < 4; t++) {
            int col = wn * 32 + (t >> 1) * 16 + (t & 1) * 8 + kc;
            *(float2*)&slab[g * 64 + col]       = make_float2(accO[t][0], accO[t][1]);
            *(float2*)&slab[(g + 8) * 64 + col] = make_float2(accO[t][2], accO[t][3]);
        }
    }
    __syncthreads();
    if (wk == 0) {
        #pragma unroll
        for (int t = 0; t < 4; t++) {
            int col = wn * 32 + (t >> 1) * 16 + (t & 1) * 8 + kc;
            float2 v0 = make_float2(accO[t][0], accO[t][1]);
            float2 v1 = make_float2(accO[t][2], accO[t][3]);
            #pragma unroll
            for (int s = 0; s < 3; s++) {
                float2 p0 = *(float2*)&red[s * 1024 + g * 64 + col];
                float2 p1 = *(float2*)&red[s * 1024 + (g + 8) * 64 + col];
                v0.x += p0.x; v0.y += p0.y;
                v1.x += p1.x; v1.y += p1.y;
            }
            int orow = q0 + g;
            int ocol = hh * 64 + col;
            float* dst = attnout + (size_t)(bb * NSEQ + orow) * 512 + ocol;
            *(float2*)dst             = v0;
            *(float2*)(dst + 8 * 512) = v1;
        }
    }
}

// =============================================================================
extern "C" void kernel_launch(void* const* d_in, const int* in_sizes, int n_in,
                              void* d_out, int out_size)
{
    const float* queries = (const float*)d_in[0];
    const float* keys    = (const float*)d_in[1];
    const float* values  = (const float*)d_in[2];
    const float* relw    = (const float*)d_in[3];
    const float* Wq = (const float*)d_in[4];
    const float* bq = (const float*)d_in[5];
    const float* Wk = (const float*)d_in[6];
    const float* bk = (const float*)d_in[7];
    const float* Wv = (const float*)d_in[8];
    const float* bv = (const float*)d_in[9];
    const float* Wo = (const float*)d_in[10];
    const float* bo = (const float*)d_in[11];

    float* out_main = (float*)d_out;
    float* out_mn   = (float*)d_out + (size_t)BATCH * NSEQ * DM;

    __nv_bfloat16 *qhi, *qlo, *khi, *klo, *vhi, *vlo;
    float* gattn;
    cudaGetSymbolAddress((void**)&qhi, g_qhi);
    cudaGetSymbolAddress((void**)&qlo, g_qlo);
    cudaGetSymbolAddress((void**)&khi, g_khi);
    cudaGetSymbolAddress((void**)&klo, g_klo);
    cudaGetSymbolAddress((void**)&vhi, g_vhi);
    cudaGetSymbolAddress((void**)&vlo, g_vlo);
    cudaGetSymbolAddress((void**)&gattn, g_attn);

    cudaFuncSetAttribute(gemm_tc<0>, cudaFuncAttributeMaxDynamicSharedMemorySize, GEMM_SMEM);
    cudaFuncSetAttribute(gemm_tc<1>, cudaFuncAttributeMaxDynamicSharedMemorySize, GEMM_SMEM);
    cudaFuncSetAttribute(attn_tc, cudaFuncAttributeMaxDynamicSharedMemorySize, ATT_SMEM);

    dim3 ggrid(4, 128);

    gemm_tc<0><<<ggrid, 256, GEMM_SMEM>>>(queries, Wq, bq, nullptr, qhi, qlo);
    gemm_tc<0><<<ggrid, 256, GEMM_SMEM>>>(keys,    Wk, bk, nullptr, khi, klo);
    gemm_tc<0><<<ggrid, 256, GEMM_SMEM>>>(values,  Wv, bv, nullptr, vhi, vlo);

    attn_tc<<<dim3(64, NH, BATCH), 256, ATT_SMEM>>>(
        qhi, qlo, khi, klo, vhi, vlo, relw, out_mn, gattn);

    gemm_tc<1><<<ggrid, 256, GEMM_SMEM>>>(gattn, Wo, bo, out_main, nullptr, nullptr);
}

// round 7
// speedup vs baseline: 1.1702x; 1.1702x over previous
#include <cuda_runtime.h>
#include <cuda_bf16.h>
#include <cstdint>
#include <math.h>

#define BATCH 16
#define NSEQ  1024
#define NH    8
#define HD    64
#define DM    512

// ---------------- scratch (static device arrays; no allocation) ----------------
#define QKV_ELEMS (BATCH*NH*NSEQ*HD)
__device__ __nv_bfloat16 g_qhi[QKV_ELEMS];
__device__ __nv_bfloat16 g_qlo[QKV_ELEMS];
__device__ __nv_bfloat16 g_khi[QKV_ELEMS];
__device__ __nv_bfloat16 g_klo[QKV_ELEMS];
__device__ __nv_bfloat16 g_vhi[QKV_ELEMS];
__device__ __nv_bfloat16 g_vlo[QKV_ELEMS];
__device__ float g_attn[BATCH*NSEQ*DM];

// =============================================================================
// helpers
// =============================================================================
__device__ __forceinline__ uint32_t smem_u32(const void* p) {
    uint32_t a;
    asm("{ .reg .u64 t; cvta.to.shared.u64 t, %1; cvt.u32.u64 %0, t; }"
        : "=r"(a) : "l"(p));
    return a;
}
__device__ __forceinline__ void ldsm_x4(uint32_t* r, uint32_t addr) {
    asm volatile("ldmatrix.sync.aligned.m8n8.x4.shared.b16 {%0,%1,%2,%3}, [%4];"
        : "=r"(r[0]), "=r"(r[1]), "=r"(r[2]), "=r"(r[3]) : "r"(addr));
}
__device__ __forceinline__ void ldsm_x4t(uint32_t* r, uint32_t addr) {
    asm volatile("ldmatrix.sync.aligned.m8n8.x4.trans.shared.b16 {%0,%1,%2,%3}, [%4];"
        : "=r"(r[0]), "=r"(r[1]), "=r"(r[2]), "=r"(r[3]) : "r"(addr));
}
__device__ __forceinline__ void mma_bf16(float* c, const uint32_t* a,
                                         uint32_t b0, uint32_t b1) {
    asm volatile(
        "mma.sync.aligned.m16n8k16.row.col.f32.bf16.bf16.f32 "
        "{%0,%1,%2,%3}, {%4,%5,%6,%7}, {%8,%9}, {%0,%1,%2,%3};"
        : "+f"(c[0]), "+f"(c[1]), "+f"(c[2]), "+f"(c[3])
        : "r"(a[0]), "r"(a[1]), "r"(a[2]), "r"(a[3]), "r"(b0), "r"(b1));
}
__device__ __forceinline__ void cp16(uint32_t dst, const void* src) {
    asm volatile("cp.async.cg.shared.global [%0], [%1], 16;" :: "r"(dst), "l"(src));
}
#define CP_COMMIT() asm volatile("cp.async.commit_group;" ::: "memory")
#define CP_WAIT0()  asm volatile("cp.async.wait_group 0;" ::: "memory")

__device__ __forceinline__ uint32_t pack_bf16_res(float a, float b, float& ra, float& rb) {
    __nv_bfloat16 ha = __float2bfloat16(a), hb = __float2bfloat16(b);
    ra = a - __bfloat162float(ha);
    rb = b - __bfloat162float(hb);
    __nv_bfloat162 p(ha, hb);
    return *reinterpret_cast<uint32_t*>(&p);
}
__device__ __forceinline__ uint32_t pack_bf16(float a, float b) {
    __nv_bfloat162 p(__float2bfloat16(a), __float2bfloat16(b));
    return *reinterpret_cast<uint32_t*>(&p);
}
// word: low16 = bf16 hi(p), high16 = bf16 lo-residual(p)
__device__ __forceinline__ uint32_t packP(float p) {
    __nv_bfloat16 hi = __float2bfloat16(p);
    __nv_bfloat16 lo = __float2bfloat16(p - __bfloat162float(hi));
    uint16_t hb = *reinterpret_cast<uint16_t*>(&hi);
    uint16_t lb = *reinterpret_cast<uint16_t*>(&lo);
    return (uint32_t)hb | ((uint32_t)lb << 16);
}

// =============================================================================
// Tensor-core (HMMA) GEMM: C[16384,512] = X @ W + bias, bf16 split-3.
// (unchanged, known good)
// =============================================================================
#define ASTRIDE 40
#define BSTRIDE 136
#define A_BYTES (128*ASTRIDE*2)
#define B_BYTES (32*BSTRIDE*2)
#define OFF_ALO A_BYTES
#define OFF_BHI (2*A_BYTES)
#define OFF_BLO (2*A_BYTES + B_BYTES)
#define GBUF    (2*A_BYTES + 2*B_BYTES)
#define GEMM_SMEM (2*GBUF)

template<int MODE>
__global__ __launch_bounds__(256, 1) void gemm_tc(
    const float* __restrict__ X, const float* __restrict__ W,
    const float* __restrict__ bias, float* __restrict__ out,
    __nv_bfloat16* __restrict__ ohi, __nv_bfloat16* __restrict__ olo)
{
    extern __shared__ char smem[];
    const uint32_t sb = smem_u32(smem);
    const int tid  = threadIdx.x;
    const int wid  = tid >> 5, lane = tid & 31;
    const int wm   = wid >> 2;
    const int wn   = wid & 3;
    const int n0   = blockIdx.x * 128;
    const int m0   = blockIdx.y * 128;

    float acc[4][4][4];
    #pragma unroll
    for (int i = 0; i < 4; i++)
        #pragma unroll
        for (int j = 0; j < 4; j++)
            #pragma unroll
            for (int k = 0; k < 4; k++) acc[i][j][k] = 0.f;

    float4 ra[4], rb[4];

    auto gload = [&](int c) {
        const int k0 = c * 32;
        #pragma unroll
        for (int i = 0; i < 4; i++) {
            int idx = i * 256 + tid;
            int row = idx >> 3, col = (idx & 7) * 4;
            ra[i] = *(const float4*)&X[(size_t)(m0 + row) * 512 + k0 + col];
        }
        #pragma unroll
        for (int i = 0; i < 4; i++) {
            int idx = i * 256 + tid;
            int kk = idx >> 5, col = (idx & 31) * 4;
            rb[i] = *(const float4*)&W[(size_t)(k0 + kk) * 512 + n0 + col];
        }
    };

    auto cstore = [&](int buf) {
        char* bp = smem + buf * GBUF;
        #pragma unroll
        for (int i = 0; i < 4; i++) {
            int idx = i * 256 + tid;
            int row = idx >> 3, col = (idx & 7) * 4;
            float r0, r1, r2, r3;
            uint2 hi, lo;
            hi.x = pack_bf16_res(ra[i].x, ra[i].y, r0, r1);
            hi.y = pack_bf16_res(ra[i].z, ra[i].w, r2, r3);
            lo.x = pack_bf16(r0, r1);
            lo.y = pack_bf16(r2, r3);
            uint32_t off = (uint32_t)(row * ASTRIDE + col) * 2;
            *(uint2*)(bp + off)           = hi;
            *(uint2*)(bp + OFF_ALO + off) = lo;
        }
        #pragma unroll
        for (int i = 0; i < 4; i++) {
            int idx = i * 256 + tid;
            int kk = idx >> 5, col = (idx & 31) * 4;
            float r0, r1, r2, r3;
            uint2 hi, lo;
            hi.x = pack_bf16_res(rb[i].x, rb[i].y, r0, r1);
            hi.y = pack_bf16_res(rb[i].z, rb[i].w, r2, r3);
            lo.x = pack_bf16(r0, r1);
            lo.y = pack_bf16(r2, r3);
            uint32_t off = (uint32_t)(kk * BSTRIDE + col) * 2;
            *(uint2*)(bp + OFF_BHI + off) = hi;
            *(uint2*)(bp + OFF_BLO + off) = lo;
        }
    };

    const uint32_t aLane = (uint32_t)((wm * 64 + (lane & 15)) * ASTRIDE + (lane >> 4) * 8) * 2;
    const uint32_t bLane = (uint32_t)((lane & 15) * BSTRIDE + wn * 32 + (lane >> 4) * 8) * 2;

    auto compute = [&](int buf) {
        const uint32_t base = sb + buf * GBUF;
        #pragma unroll
        for (int ks = 0; ks < 2; ks++) {
            uint32_t ah[4][4], al[4][4], bh[2][4], bl[2][4];
            #pragma unroll
            for (int mt = 0; mt < 4; mt++) {
                uint32_t ad = base + aLane + (uint32_t)(mt * 16 * ASTRIDE + ks * 16) * 2;
                ldsm_x4(ah[mt], ad);
                ldsm_x4(al[mt], ad + OFF_ALO);
            }
            #pragma unroll
            for (int nt = 0; nt < 2; nt++) {
                uint32_t bd = base + OFF_BHI + bLane +
                              (uint32_t)(ks * 16 * BSTRIDE + nt * 16) * 2;
                ldsm_x4t(bh[nt], bd);
                ldsm_x4t(bl[nt], bd + B_BYTES);
            }
            #pragma unroll
            for (int mt = 0; mt < 4; mt++) {
                #pragma unroll
                for (int n8 = 0; n8 < 4; n8++) {
                    const int nt = n8 >> 1, hf = (n8 & 1) * 2;
                    float* c = acc[mt][n8];
                    mma_bf16(c, ah[mt], bh[nt][hf], bh[nt][hf + 1]);
                    mma_bf16(c, ah[mt], bl[nt][hf], bl[nt][hf + 1]);
                    mma_bf16(c, al[mt], bh[nt][hf], bh[nt][hf + 1]);
                }
            }
        }
    };

    gload(0);
    cstore(0);
    __syncthreads();
    for (int c = 0; c < 16; c++) {
        if (c < 15) gload(c + 1);
        compute(c & 1);
        if (c < 15) {
            cstore((c + 1) & 1);
            __syncthreads();
        }
    }

    const int gid = lane >> 2;
    const int cid = (lane & 3) * 2;
    #pragma unroll
    for (int mt = 0; mt < 4; mt++) {
        #pragma unroll
        for (int n8 = 0; n8 < 4; n8++) {
            int row = m0 + wm * 64 + mt * 16 + gid;
            int col = n0 + wn * 32 + n8 * 8 + cid;
            float b0 = __ldg(&bias[col]), b1 = __ldg(&bias[col + 1]);
            float2 v0 = make_float2(acc[mt][n8][0] + b0, acc[mt][n8][1] + b1);
            float2 v1 = make_float2(acc[mt][n8][2] + b0, acc[mt][n8][3] + b1);
            if (MODE == 0) {
                int h = col >> 6, d = col & 63;
                #pragma unroll
                for (int rr = 0; rr < 2; rr++) {
                    int r = row + rr * 8;
                    float2 v = rr ? v1 : v0;
                    int bi = r >> 10, ni = r & 1023;
                    size_t idx = (size_t)(((bi * NH + h) << 10) + ni) * 64 + d;
                    float e0, e1;
                    uint32_t hi = pack_bf16_res(v.x, v.y, e0, e1);
                    uint32_t lo = pack_bf16(e0, e1);
                    *(uint32_t*)&ohi[idx] = hi;
                    *(uint32_t*)&olo[idx] = lo;
                }
            } else {
                *(float2*)&out[(size_t)row * 512 + col]       = v0;
                *(float2*)&out[(size_t)(row + 8) * 512 + col] = v1;
            }
        }
    }
}

// =============================================================================
// Register-resident fused attention. 512 threads / 16 warps, 32 q-rows/CTA.
// Scores never touch SMEM: QK C-frags -> softmax in regs -> P A-frags -> PV.
// Warp (wmq = wid>>3, wq = wid&7): m16 slab x 16-col slice of each 128-chunk.
// =============================================================================
#define KVSTR   144
#define ATT_KVSZ 36864           // 128 rows * 144B * 2 planes
#define ATT_LO   18432
#define ATT_Q    (2*ATT_KVSZ)    // 73728
#define ATT_QLO  4608
#define ATT_PM   (ATT_Q + 9216)  // 82944: pmax[32][8] f32
#define ATT_PS   (ATT_PM + 1024) // psum[32][8]
#define ATT_SMEM (ATT_PS + 1024) // 84992

__global__ __launch_bounds__(512, 1) void attn_tc(
    const __nv_bfloat16* __restrict__ qhi, const __nv_bfloat16* __restrict__ qlo,
    const __nv_bfloat16* __restrict__ khi, const __nv_bfloat16* __restrict__ klo,
    const __nv_bfloat16* __restrict__ vhi, const __nv_bfloat16* __restrict__ vlo,
    const float* __restrict__ gw, float* __restrict__ mn,
    float* __restrict__ attnout)
{
    extern __shared__ char smem[];
    const uint32_t sb = smem_u32(smem);
    float* pmaxs = (float*)(smem + ATT_PM);
    float* psums = (float*)(smem + ATT_PS);

    const int tid = threadIdx.x, wid = tid >> 5, lane = tid & 31;
    const int wmq = wid >> 3;          // m half (16 rows)
    const int wq  = wid & 7;           // 16-col slice of each 128 chunk
    const int q0 = blockIdx.x * 32, hh = blockIdx.y, bb = blockIdx.z;
    const size_t bhBase = (size_t)(bb * NH + hh) * NSEQ;

    // chunk loader: 128 rows x 64 cols, hi+lo planes
    auto loadChunk = [&](const __nv_bfloat16* hi, const __nv_bfloat16* lo,
                         int kb, int buf) {
        uint32_t dst = sb + buf * ATT_KVSZ;
        const __nv_bfloat16* sh = hi + (bhBase + kb * 128) * 64;
        const __nv_bfloat16* sl = lo + (bhBase + kb * 128) * 64;
        #pragma unroll
        for (int i = 0; i < 2; i++) {
            int idx = i * 512 + tid;
            int row = idx >> 3, col = (idx & 7) * 8;
            uint32_t d = dst + row * KVSTR + col * 2;
            cp16(d,          sh + row * 64 + col);
            cp16(d + ATT_LO, sl + row * 64 + col);
        }
        CP_COMMIT();
    };

    loadChunk(khi, klo, 0, 0);

    // ---- stage Q tile (32x64 hi/lo) ----
    {
        int pos = tid & 255;
        int row = pos >> 3, col = (pos & 7) * 8;
        size_t g = (bhBase + q0 + row) * 64 + col;
        if (tid < 256)
            *(uint4*)(smem + ATT_Q + row * KVSTR + col * 2)           = *(const uint4*)&qhi[g];
        else
            *(uint4*)(smem + ATT_Q + ATT_QLO + row * KVSTR + col * 2) = *(const uint4*)&qlo[g];
    }
    __syncthreads();

    // ---- Q fragments (m16 x k64 for this m-half) ----
    uint32_t aQh[4][4], aQl[4][4];
    {
        const uint32_t qaddr = sb + ATT_Q +
            ((uint32_t)((wmq * 16 + (lane & 15)) * 72) + (lane >> 4) * 8) * 2;
        #pragma unroll
        for (int ks = 0; ks < 4; ks++) {
            ldsm_x4(aQh[ks], qaddr + ks * 32);
            ldsm_x4(aQl[ks], qaddr + ks * 32 + ATT_QLO);
        }
    }

    // ================= QK^T : scores stay in registers =================
    // s[kb][nt*4 + {0,1}] = rows g   cols kb*128+wq*16+nt*8+(lane&3)*2 +{0,1}
    // s[kb][nt*4 + {2,3}] = rows g+8 same cols
    float s[8][8];
    for (int kb = 0; kb < 8; kb++) {
        CP_WAIT0();
        __syncthreads();
        if (kb < 7) loadChunk(khi, klo, kb + 1, (kb + 1) & 1);

        const uint32_t baddr = sb + (kb & 1) * ATT_KVSZ +
            ((uint32_t)((wq * 16 + (lane & 15)) * 72) + (lane >> 4) * 8) * 2;

        float a0[4] = {0.f, 0.f, 0.f, 0.f};
        float a1[4] = {0.f, 0.f, 0.f, 0.f};
        #pragma unroll
        for (int ks = 0; ks < 4; ks++) {
            uint32_t bh[4], bl[4];
            ldsm_x4(bh, baddr + ks * 32);
            ldsm_x4(bl, baddr + ks * 32 + ATT_LO);
            mma_bf16(a0, aQh[ks], bh[0], bh[2]);
            mma_bf16(a0, aQh[ks], bl[0], bl[2]);
            mma_bf16(a0, aQl[ks], bh[0], bh[2]);
            mma_bf16(a1, aQh[ks], bh[1], bh[3]);
            mma_bf16(a1, aQh[ks], bl[1], bl[3]);
            mma_bf16(a1, aQl[ks], bh[1], bh[3]);
        }
        #pragma unroll
        for (int j = 0; j < 4; j++) { s[kb][j] = a0[j]; s[kb][4 + j] = a1[j]; }
    }

    // prefetch V chunk 0 (overlaps softmax)
    loadChunk(vhi, vlo, 0, 0);

    // ================= softmax in registers =================
    const int g   = lane >> 2;
    const int c2  = (lane & 3) * 2;
    const int rl0 = wmq * 16 + g;              // CTA-local rows rl0, rl0+8
    const size_t grow0 = (bhBase + q0 + rl0) << 10;
    const float* w0base = gw + grow0;
    const float* w1base = gw + grow0 + (8 << 10);

    float m0 = -1e30f, m1 = -1e30f;
    #pragma unroll
    for (int kb = 0; kb < 8; kb++) {
        #pragma unroll
        for (int nt = 0; nt < 2; nt++) {
            int col = kb * 128 + wq * 16 + nt * 8 + c2;
            float2 wa = *(const float2*)&w0base[col];
            float2 wb = *(const float2*)&w1base[col];
            int j = nt * 4;
            s[kb][j + 0] = s[kb][j + 0] * 0.125f + __logf(fmaxf(wa.x, 1e-6f));
            s[kb][j + 1] = s[kb][j + 1] * 0.125f + __logf(fmaxf(wa.y, 1e-6f));
            s[kb][j + 2] = s[kb][j + 2] * 0.125f + __logf(fmaxf(wb.x, 1e-6f));
            s[kb][j + 3] = s[kb][j + 3] * 0.125f + __logf(fmaxf(wb.y, 1e-6f));
            m0 = fmaxf(m0, fmaxf(s[kb][j + 0], s[kb][j + 1]));
            m1 = fmaxf(m1, fmaxf(s[kb][j + 2], s[kb][j + 3]));
        }
    }
    m0 = fmaxf(m0, __shfl_xor_sync(0xffffffffu, m0, 1));
    m0 = fmaxf(m0, __shfl_xor_sync(0xffffffffu, m0, 2));
    m1 = fmaxf(m1, __shfl_xor_sync(0xffffffffu, m1, 1));
    m1 = fmaxf(m1, __shfl_xor_sync(0xffffffffu, m1, 2));
    if ((lane & 3) == 0) {
        pmaxs[rl0 * 8 + wq]       = m0;
        pmaxs[(rl0 + 8) * 8 + wq] = m1;
    }
    __syncthreads();
    {
        float fm0 = -1e30f, fm1 = -1e30f;
        #pragma unroll
        for (int i = 0; i < 8; i++) {
            fm0 = fmaxf(fm0, pmaxs[rl0 * 8 + i]);
            fm1 = fmaxf(fm1, pmaxs[(rl0 + 8) * 8 + i]);
        }
        m0 = fm0; m1 = fm1;
    }
    float sum0 = 0.f, sum1 = 0.f;
    #pragma unroll
    for (int kb = 0; kb < 8; kb++) {
        #pragma unroll
        for (int j = 0; j < 8; j++) {
            float e = __expf(s[kb][j] - ((j & 2) ? m1 : m0));
            s[kb][j] = e;
            if (j & 2) sum1 += e; else sum0 += e;
        }
    }
    sum0 += __shfl_xor_sync(0xffffffffu, sum0, 1);
    sum0 += __shfl_xor_sync(0xffffffffu, sum0, 2);
    sum1 += __shfl_xor_sync(0xffffffffu, sum1, 1);
    sum1 += __shfl_xor_sync(0xffffffffu, sum1, 2);
    if ((lane & 3) == 0) {
        psums[rl0 * 8 + wq]       = sum0;
        psums[(rl0 + 8) * 8 + wq] = sum1;
    }
    __syncthreads();
    {
        float t0 = 0.f, t1 = 0.f;
        #pragma unroll
        for (int i = 0; i < 8; i++) {
            t0 += psums[rl0 * 8 + i];
            t1 += psums[(rl0 + 8) * 8 + i];
        }
        sum0 = 1.f / t0; sum1 = 1.f / t1;
    }

    // normalize, write mn, pack P hi|lo in place
    float* mrow0 = mn + grow0;
    float* mrow1 = mn + grow0 + (8 << 10);
    #pragma unroll
    for (int kb = 0; kb < 8; kb++) {
        #pragma unroll
        for (int nt = 0; nt < 2; nt++) {
            int col = kb * 128 + wq * 16 + nt * 8 + c2;
            int j = nt * 4;
            float p0 = s[kb][j + 0] * sum0;
            float p1 = s[kb][j + 1] * sum0;
            float p2 = s[kb][j + 2] * sum1;
            float p3 = s[kb][j + 3] * sum1;
            *(float2*)&mrow0[col] = make_float2(p0, p1);
            *(float2*)&mrow1[col] = make_float2(p2, p3);
            s[kb][j + 0] = __uint_as_float(packP(p0));
            s[kb][j + 1] = __uint_as_float(packP(p1));
            s[kb][j + 2] = __uint_as_float(packP(p2));
            s[kb][j + 3] = __uint_as_float(packP(p3));
        }
    }

    // ================= P @ V : P from registers, warp = k16 slice =============
    float accO[8][4];
    #pragma unroll
    for (int t = 0; t < 8; t++)
        #pragma unroll
        for (int j = 0; j < 4; j++) accO[t][j] = 0.f;

    for (int kb = 0; kb < 8; kb++) {
        CP_WAIT0();
        __syncthreads();
        if (kb < 7) loadChunk(vhi, vlo, kb + 1, (kb + 1) & 1);

        // A-frags from packed P words
        uint32_t ah[4], al[4];
        {
            uint32_t w0 = __float_as_uint(s[kb][0]), w1 = __float_as_uint(s[kb][1]);
            uint32_t w2 = __float_as_uint(s[kb][2]), w3 = __float_as_uint(s[kb][3]);
            uint32_t w4 = __float_as_uint(s[kb][4]), w5 = __float_as_uint(s[kb][5]);
            uint32_t w6 = __float_as_uint(s[kb][6]), w7 = __float_as_uint(s[kb][7]);
            ah[0] = __byte_perm(w0, w1, 0x5410); al[0] = __byte_perm(w0, w1, 0x7632);
            ah[1] = __byte_perm(w2, w3, 0x5410); al[1] = __byte_perm(w2, w3, 0x7632);
            ah[2] = __byte_perm(w4, w5, 0x5410); al[2] = __byte_perm(w4, w5, 0x7632);
            ah[3] = __byte_perm(w6, w7, 0x5410); al[3] = __byte_perm(w6, w7, 0x7632);
        }

        const uint32_t vbase = sb + (kb & 1) * ATT_KVSZ;
        #pragma unroll
        for (int ng = 0; ng < 4; ng++) {
            uint32_t vaddr = vbase +
                ((uint32_t)((wq * 16 + (lane & 15)) * 72) +
                 ng * 16 + (lane >> 4) * 8) * 2;
            uint32_t bh[4], bl[4];
            ldsm_x4t(bh, vaddr);
            ldsm_x4t(bl, vaddr + ATT_LO);
            float* c0 = accO[ng * 2];
            float* c1 = accO[ng * 2 + 1];
            mma_bf16(c0, ah, bh[0], bh[1]);
            mma_bf16(c0, ah, bl[0], bl[1]);
            mma_bf16(c0, al, bh[0], bh[1]);
            mma_bf16(c1, ah, bh[2], bh[3]);
            mma_bf16(c1, ah, bl[2], bl[3]);
            mma_bf16(c1, al, bh[2], bh[3]);
        }
    }
    __syncthreads();   // V reads done; reuse KV region as reduction buffer

    // ---- 8-way k-slice reduction via smem ----
    float* red = (float*)smem;          // 16 slabs x 16x64 f32 = 64KB
    {
        float* slab = red + wid * 1024;
        #pragma unroll
        for (int t = 0; t < 8; t++) {
            int col = (t >> 1) * 16 + (t & 1) * 8 + c2;
            *(float2*)&slab[g * 64 + col]       = make_float2(accO[t][0], accO[t][1]);
            *(float2*)&slab[(g + 8) * 64 + col] = make_float2(accO[t][2], accO[t][3]);
        }
    }
    __syncthreads();
    {
        int row = tid >> 4;             // 0..31
        int c4  = (tid & 15) * 4;
        int h   = row >> 4, rl = row & 15;
        float4 v = make_float4(0.f, 0.f, 0.f, 0.f);
        #pragma unroll
        for (int w2 = 0; w2 < 8; w2++) {
            float4 p = *(float4*)&red[(h * 8 + w2) * 1024 + rl * 64 + c4];
            v.x += p.x; v.y += p.y; v.z += p.z; v.w += p.w;
        }
        float* dst = attnout + (size_t)(bb * NSEQ + q0 + row) * 512 + hh * 64 + c4;
        *(float4*)dst = v;
    }
}

// =============================================================================
extern "C" void kernel_launch(void* const* d_in, const int* in_sizes, int n_in,
                              void* d_out, int out_size)
{
    const float* queries = (const float*)d_in[0];
    const float* keys    = (const float*)d_in[1];
    const float* values  = (const float*)d_in[2];
    const float* relw    = (const float*)d_in[3];
    const float* Wq = (const float*)d_in[4];
    const float* bq = (const float*)d_in[5];
    const float* Wk = (const float*)d_in[6];
    const float* bk = (const float*)d_in[7];
    const float* Wv = (const float*)d_in[8];
    const float* bv = (const float*)d_in[9];
    const float* Wo = (const float*)d_in[10];
    const float* bo = (const float*)d_in[11];

    float* out_main = (float*)d_out;
    float* out_mn   = (float*)d_out + (size_t)BATCH * NSEQ * DM;

    __nv_bfloat16 *qhi, *qlo, *khi, *klo, *vhi, *vlo;
    float* gattn;
    cudaGetSymbolAddress((void**)&qhi, g_qhi);
    cudaGetSymbolAddress((void**)&qlo, g_qlo);
    cudaGetSymbolAddress((void**)&khi, g_khi);
    cudaGetSymbolAddress((void**)&klo, g_klo);
    cudaGetSymbolAddress((void**)&vhi, g_vhi);
    cudaGetSymbolAddress((void**)&vlo, g_vlo);
    cudaGetSymbolAddress((void**)&gattn, g_attn);

    cudaFuncSetAttribute(gemm_tc<0>, cudaFuncAttributeMaxDynamicSharedMemorySize, GEMM_SMEM);
    cudaFuncSetAttribute(gemm_tc<1>, cudaFuncAttributeMaxDynamicSharedMemorySize, GEMM_SMEM);
    cudaFuncSetAttribute(attn_tc, cudaFuncAttributeMaxDynamicSharedMemorySize, ATT_SMEM);

    dim3 ggrid(4, 128);

    gemm_tc<0><<<ggrid, 256, GEMM_SMEM>>>(queries, Wq, bq, nullptr, qhi, qlo);
    gemm_tc<0><<<ggrid, 256, GEMM_SMEM>>>(keys,    Wk, bk, nullptr, khi, klo);
    gemm_tc<0><<<ggrid, 256, GEMM_SMEM>>>(values,  Wv, bv, nullptr, vhi, vlo);

    attn_tc<<<dim3(32, NH, BATCH), 512, ATT_SMEM>>>(
        qhi, qlo, khi, klo, vhi, vlo, relw, out_mn, gattn);

    gemm_tc<1><<<ggrid, 256, GEMM_SMEM>>>(gattn, Wo, bo, out_main, nullptr, nullptr);
}

// round 8
// speedup vs baseline: 1.2597x; 1.0765x over previous
#include <cuda_runtime.h>
#include <cuda_bf16.h>
#include <cstdint>
#include <math.h>

#define BATCH 16
#define NSEQ  1024
#define NH    8
#define HD    64
#define DM    512

// ---------------- scratch (static device arrays; no allocation) ----------------
#define QKV_ELEMS (BATCH*NH*NSEQ*HD)
__device__ __nv_bfloat16 g_qhi[QKV_ELEMS];
__device__ __nv_bfloat16 g_qlo[QKV_ELEMS];
__device__ __nv_bfloat16 g_khi[QKV_ELEMS];
__device__ __nv_bfloat16 g_klo[QKV_ELEMS];
__device__ __nv_bfloat16 g_vhi[QKV_ELEMS];
__device__ __nv_bfloat16 g_vlo[QKV_ELEMS];
__device__ float g_attn[BATCH*NSEQ*DM];

// =============================================================================
// helpers
// =============================================================================
__device__ __forceinline__ uint32_t smem_u32(const void* p) {
    uint32_t a;
    asm("{ .reg .u64 t; cvta.to.shared.u64 t, %1; cvt.u32.u64 %0, t; }"
        : "=r"(a) : "l"(p));
    return a;
}
__device__ __forceinline__ void ldsm_x4(uint32_t* r, uint32_t addr) {
    asm volatile("ldmatrix.sync.aligned.m8n8.x4.shared.b16 {%0,%1,%2,%3}, [%4];"
        : "=r"(r[0]), "=r"(r[1]), "=r"(r[2]), "=r"(r[3]) : "r"(addr));
}
__device__ __forceinline__ void ldsm_x4t(uint32_t* r, uint32_t addr) {
    asm volatile("ldmatrix.sync.aligned.m8n8.x4.trans.shared.b16 {%0,%1,%2,%3}, [%4];"
        : "=r"(r[0]), "=r"(r[1]), "=r"(r[2]), "=r"(r[3]) : "r"(addr));
}
__device__ __forceinline__ void mma_bf16(float* c, const uint32_t* a,
                                         uint32_t b0, uint32_t b1) {
    asm volatile(
        "mma.sync.aligned.m16n8k16.row.col.f32.bf16.bf16.f32 "
        "{%0,%1,%2,%3}, {%4,%5,%6,%7}, {%8,%9}, {%0,%1,%2,%3};"
        : "+f"(c[0]), "+f"(c[1]), "+f"(c[2]), "+f"(c[3])
        : "r"(a[0]), "r"(a[1]), "r"(a[2]), "r"(a[3]), "r"(b0), "r"(b1));
}
__device__ __forceinline__ void cp16(uint32_t dst, const void* src) {
    asm volatile("cp.async.cg.shared.global [%0], [%1], 16;" :: "r"(dst), "l"(src));
}
#define CP_COMMIT() asm volatile("cp.async.commit_group;" ::: "memory")
#define CP_WAIT0()  asm volatile("cp.async.wait_group 0;" ::: "memory")

__device__ __forceinline__ uint32_t pack_bf16_res(float a, float b, float& ra, float& rb) {
    __nv_bfloat16 ha = __float2bfloat16(a), hb = __float2bfloat16(b);
    ra = a - __bfloat162float(ha);
    rb = b - __bfloat162float(hb);
    __nv_bfloat162 p(ha, hb);
    return *reinterpret_cast<uint32_t*>(&p);
}
__device__ __forceinline__ uint32_t pack_bf16(float a, float b) {
    __nv_bfloat162 p(__float2bfloat16(a), __float2bfloat16(b));
    return *reinterpret_cast<uint32_t*>(&p);
}
// word: low16 = bf16 hi(p), high16 = bf16 lo-residual(p)
__device__ __forceinline__ uint32_t packP(float p) {
    __nv_bfloat16 hi = __float2bfloat16(p);
    __nv_bfloat16 lo = __float2bfloat16(p - __bfloat162float(hi));
    uint16_t hb = *reinterpret_cast<uint16_t*>(&hi);
    uint16_t lb = *reinterpret_cast<uint16_t*>(&lo);
    return (uint32_t)hb | ((uint32_t)lb << 16);
}

// =============================================================================
// Tensor-core (HMMA) GEMM: C[16384,512] = X @ W + bias, bf16 split-3.
// (unchanged, known good)
// =============================================================================
#define ASTRIDE 40
#define BSTRIDE 136
#define A_BYTES (128*ASTRIDE*2)
#define B_BYTES (32*BSTRIDE*2)
#define OFF_ALO A_BYTES
#define OFF_BHI (2*A_BYTES)
#define OFF_BLO (2*A_BYTES + B_BYTES)
#define GBUF    (2*A_BYTES + 2*B_BYTES)
#define GEMM_SMEM (2*GBUF)

template<int MODE>
__global__ __launch_bounds__(256, 1) void gemm_tc(
    const float* __restrict__ X, const float* __restrict__ W,
    const float* __restrict__ bias, float* __restrict__ out,
    __nv_bfloat16* __restrict__ ohi, __nv_bfloat16* __restrict__ olo)
{
    extern __shared__ char smem[];
    const uint32_t sb = smem_u32(smem);
    const int tid  = threadIdx.x;
    const int wid  = tid >> 5, lane = tid & 31;
    const int wm   = wid >> 2;
    const int wn   = wid & 3;
    const int n0   = blockIdx.x * 128;
    const int m0   = blockIdx.y * 128;

    float acc[4][4][4];
    #pragma unroll
    for (int i = 0; i < 4; i++)
        #pragma unroll
        for (int j = 0; j < 4; j++)
            #pragma unroll
            for (int k = 0; k < 4; k++) acc[i][j][k] = 0.f;

    float4 ra[4], rb[4];

    auto gload = [&](int c) {
        const int k0 = c * 32;
        #pragma unroll
        for (int i = 0; i < 4; i++) {
            int idx = i * 256 + tid;
            int row = idx >> 3, col = (idx & 7) * 4;
            ra[i] = *(const float4*)&X[(size_t)(m0 + row) * 512 + k0 + col];
        }
        #pragma unroll
        for (int i = 0; i < 4; i++) {
            int idx = i * 256 + tid;
            int kk = idx >> 5, col = (idx & 31) * 4;
            rb[i] = *(const float4*)&W[(size_t)(k0 + kk) * 512 + n0 + col];
        }
    };

    auto cstore = [&](int buf) {
        char* bp = smem + buf * GBUF;
        #pragma unroll
        for (int i = 0; i < 4; i++) {
            int idx = i * 256 + tid;
            int row = idx >> 3, col = (idx & 7) * 4;
            float r0, r1, r2, r3;
            uint2 hi, lo;
            hi.x = pack_bf16_res(ra[i].x, ra[i].y, r0, r1);
            hi.y = pack_bf16_res(ra[i].z, ra[i].w, r2, r3);
            lo.x = pack_bf16(r0, r1);
            lo.y = pack_bf16(r2, r3);
            uint32_t off = (uint32_t)(row * ASTRIDE + col) * 2;
            *(uint2*)(bp + off)           = hi;
            *(uint2*)(bp + OFF_ALO + off) = lo;
        }
        #pragma unroll
        for (int i = 0; i < 4; i++) {
            int idx = i * 256 + tid;
            int kk = idx >> 5, col = (idx & 31) * 4;
            float r0, r1, r2, r3;
            uint2 hi, lo;
            hi.x = pack_bf16_res(rb[i].x, rb[i].y, r0, r1);
            hi.y = pack_bf16_res(rb[i].z, rb[i].w, r2, r3);
            lo.x = pack_bf16(r0, r1);
            lo.y = pack_bf16(r2, r3);
            uint32_t off = (uint32_t)(kk * BSTRIDE + col) * 2;
            *(uint2*)(bp + OFF_BHI + off) = hi;
            *(uint2*)(bp + OFF_BLO + off) = lo;
        }
    };

    const uint32_t aLane = (uint32_t)((wm * 64 + (lane & 15)) * ASTRIDE + (lane >> 4) * 8) * 2;
    const uint32_t bLane = (uint32_t)((lane & 15) * BSTRIDE + wn * 32 + (lane >> 4) * 8) * 2;

    auto compute = [&](int buf) {
        const uint32_t base = sb + buf * GBUF;
        #pragma unroll
        for (int ks = 0; ks < 2; ks++) {
            uint32_t ah[4][4], al[4][4], bh[2][4], bl[2][4];
            #pragma unroll
            for (int mt = 0; mt < 4; mt++) {
                uint32_t ad = base + aLane + (uint32_t)(mt * 16 * ASTRIDE + ks * 16) * 2;
                ldsm_x4(ah[mt], ad);
                ldsm_x4(al[mt], ad + OFF_ALO);
            }
            #pragma unroll
            for (int nt = 0; nt < 2; nt++) {
                uint32_t bd = base + OFF_BHI + bLane +
                              (uint32_t)(ks * 16 * BSTRIDE + nt * 16) * 2;
                ldsm_x4t(bh[nt], bd);
                ldsm_x4t(bl[nt], bd + B_BYTES);
            }
            #pragma unroll
            for (int mt = 0; mt < 4; mt++) {
                #pragma unroll
                for (int n8 = 0; n8 < 4; n8++) {
                    const int nt = n8 >> 1, hf = (n8 & 1) * 2;
                    float* c = acc[mt][n8];
                    mma_bf16(c, ah[mt], bh[nt][hf], bh[nt][hf + 1]);
                    mma_bf16(c, ah[mt], bl[nt][hf], bl[nt][hf + 1]);
                    mma_bf16(c, al[mt], bh[nt][hf], bh[nt][hf + 1]);
                }
            }
        }
    };

    gload(0);
    cstore(0);
    __syncthreads();
    for (int c = 0; c < 16; c++) {
        if (c < 15) gload(c + 1);
        compute(c & 1);
        if (c < 15) {
            cstore((c + 1) & 1);
            __syncthreads();
        }
    }

    const int gid = lane >> 2;
    const int cid = (lane & 3) * 2;
    #pragma unroll
    for (int mt = 0; mt < 4; mt++) {
        #pragma unroll
        for (int n8 = 0; n8 < 4; n8++) {
            int row = m0 + wm * 64 + mt * 16 + gid;
            int col = n0 + wn * 32 + n8 * 8 + cid;
            float b0 = __ldg(&bias[col]), b1 = __ldg(&bias[col + 1]);
            float2 v0 = make_float2(acc[mt][n8][0] + b0, acc[mt][n8][1] + b1);
            float2 v1 = make_float2(acc[mt][n8][2] + b0, acc[mt][n8][3] + b1);
            if (MODE == 0) {
                int h = col >> 6, d = col & 63;
                #pragma unroll
                for (int rr = 0; rr < 2; rr++) {
                    int r = row + rr * 8;
                    float2 v = rr ? v1 : v0;
                    int bi = r >> 10, ni = r & 1023;
                    size_t idx = (size_t)(((bi * NH + h) << 10) + ni) * 64 + d;
                    float e0, e1;
                    uint32_t hi = pack_bf16_res(v.x, v.y, e0, e1);
                    uint32_t lo = pack_bf16(e0, e1);
                    *(uint32_t*)&ohi[idx] = hi;
                    *(uint32_t*)&olo[idx] = lo;
                }
            } else {
                *(float2*)&out[(size_t)row * 512 + col]       = v0;
                *(float2*)&out[(size_t)(row + 8) * 512 + col] = v1;
            }
        }
    }
}

// =============================================================================
// Register-resident fused attention, phase-overlapped:
//  - gw (log-bias) cp.async'd + applied inside the QK loop
//  - mn stores + P normalization/packing inside the PV loop
//  - QK split-3 terms in 3 independent accumulator chains
// 512 threads / 16 warps, 32 q-rows/CTA.
// =============================================================================
#define KVSTR   144
#define ATT_KVSZ 36864           // 128 rows * 144B * 2 planes
#define ATT_LO   18432
#define ATT_Q    (2*ATT_KVSZ)    // 73728
#define ATT_QLO  4608
#define ATT_W    (ATT_Q + 9216)  // 82944; w chunk: 32 rows x 132 floats
#define WSTR     132
#define ATT_WSZ  (32*WSTR*4)     // 16896
#define ATT_PM   (ATT_W + 2*ATT_WSZ)   // 116736
#define ATT_PS   (ATT_PM + 1024)
#define ATT_SMEM (ATT_PS + 1024)       // 118784

__global__ __launch_bounds__(512, 1) void attn_tc(
    const __nv_bfloat16* __restrict__ qhi, const __nv_bfloat16* __restrict__ qlo,
    const __nv_bfloat16* __restrict__ khi, const __nv_bfloat16* __restrict__ klo,
    const __nv_bfloat16* __restrict__ vhi, const __nv_bfloat16* __restrict__ vlo,
    const float* __restrict__ gw, float* __restrict__ mn,
    float* __restrict__ attnout)
{
    extern __shared__ char smem[];
    const uint32_t sb = smem_u32(smem);
    float* pmaxs = (float*)(smem + ATT_PM);
    float* psums = (float*)(smem + ATT_PS);

    const int tid = threadIdx.x, wid = tid >> 5, lane = tid & 31;
    const int wmq = wid >> 3;          // m half (16 rows)
    const int wq  = wid & 7;           // 16-col slice of each 128 chunk
    const int q0 = blockIdx.x * 32, hh = blockIdx.y, bb = blockIdx.z;
    const size_t bhBase = (size_t)(bb * NH + hh) * NSEQ;

    // K/V chunk loader: 128 rows x 64 cols, hi+lo planes
    auto loadChunk = [&](const __nv_bfloat16* hi, const __nv_bfloat16* lo,
                         int kb, int buf) {
        uint32_t dst = sb + buf * ATT_KVSZ;
        const __nv_bfloat16* sh = hi + (bhBase + kb * 128) * 64;
        const __nv_bfloat16* sl = lo + (bhBase + kb * 128) * 64;
        #pragma unroll
        for (int i = 0; i < 2; i++) {
            int idx = i * 512 + tid;
            int row = idx >> 3, col = (idx & 7) * 8;
            uint32_t d = dst + row * KVSTR + col * 2;
            cp16(d,          sh + row * 64 + col);
            cp16(d + ATT_LO, sl + row * 64 + col);
        }
    };
    // w chunk loader: 32 q-rows x 128 cols fp32
    auto loadW = [&](int kb, int buf) {
        uint32_t dst = sb + ATT_W + buf * ATT_WSZ;
        const float* src = gw + ((bhBase + q0) << 10) + kb * 128;
        #pragma unroll
        for (int i = 0; i < 2; i++) {
            int idx = i * 512 + tid;
            int row = idx >> 5, col = (idx & 31) * 4;
            cp16(dst + (uint32_t)(row * WSTR + col) * 4,
                 src + ((size_t)row << 10) + col);
        }
    };

    loadChunk(khi, klo, 0, 0);
    loadW(0, 0);
    CP_COMMIT();

    // ---- stage Q tile (32x64 hi/lo) ----
    {
        int pos = tid & 255;
        int row = pos >> 3, col = (pos & 7) * 8;
        size_t g = (bhBase + q0 + row) * 64 + col;
        if (tid < 256)
            *(uint4*)(smem + ATT_Q + row * KVSTR + col * 2)           = *(const uint4*)&qhi[g];
        else
            *(uint4*)(smem + ATT_Q + ATT_QLO + row * KVSTR + col * 2) = *(const uint4*)&qlo[g];
    }
    __syncthreads();

    // ---- Q fragments (m16 x k64 for this m-half) ----
    uint32_t aQh[4][4], aQl[4][4];
    {
        const uint32_t qaddr = sb + ATT_Q +
            ((uint32_t)((wmq * 16 + (lane & 15)) * 72) + (lane >> 4) * 8) * 2;
        #pragma unroll
        for (int ks = 0; ks < 4; ks++) {
            ldsm_x4(aQh[ks], qaddr + ks * 32);
            ldsm_x4(aQl[ks], qaddr + ks * 32 + ATT_QLO);
        }
    }

    const int g   = lane >> 2;
    const int c2  = (lane & 3) * 2;
    const int rl0 = wmq * 16 + g;              // CTA-local rows rl0, rl0+8
    const size_t grow0 = (bhBase + q0 + rl0) << 10;

    // ================= QK^T + fused log-bias + running max ====================
    float s[8][8];
    float m0 = -1e30f, m1 = -1e30f;
    for (int kb = 0; kb < 8; kb++) {
        CP_WAIT0();
        __syncthreads();
        if (kb < 7) {
            loadChunk(khi, klo, kb + 1, (kb + 1) & 1);
            loadW(kb + 1, (kb + 1) & 1);
            CP_COMMIT();
        }

        const uint32_t baddr = sb + (kb & 1) * ATT_KVSZ +
            ((uint32_t)((wq * 16 + (lane & 15)) * 72) + (lane >> 4) * 8) * 2;

        // 3 independent chains per n8 tile (split terms), depth 4 each
        float t0h[4] = {0,0,0,0}, t0l[4] = {0,0,0,0}, t0m[4] = {0,0,0,0};
        float t1h[4] = {0,0,0,0}, t1l[4] = {0,0,0,0}, t1m[4] = {0,0,0,0};
        #pragma unroll
        for (int ks = 0; ks < 4; ks++) {
            uint32_t bh[4], bl[4];
            ldsm_x4(bh, baddr + ks * 32);
            ldsm_x4(bl, baddr + ks * 32 + ATT_LO);
            mma_bf16(t0h, aQh[ks], bh[0], bh[2]);
            mma_bf16(t0l, aQh[ks], bl[0], bl[2]);
            mma_bf16(t0m, aQl[ks], bh[0], bh[2]);
            mma_bf16(t1h, aQh[ks], bh[1], bh[3]);
            mma_bf16(t1l, aQh[ks], bl[1], bl[3]);
            mma_bf16(t1m, aQl[ks], bh[1], bh[3]);
        }

        // merge + fused scale/log-bias from smem W buffer
        const float* wsm = (const float*)(smem + ATT_W + (kb & 1) * ATT_WSZ);
        #pragma unroll
        for (int nt = 0; nt < 2; nt++) {
            int wcol = wq * 16 + nt * 8 + c2;
            float2 wa = *(const float2*)&wsm[rl0 * WSTR + wcol];
            float2 wb = *(const float2*)&wsm[(rl0 + 8) * WSTR + wcol];
            int j = nt * 4;
            float* ta = nt ? t1h : t0h;
            float* tb = nt ? t1l : t0l;
            float* tc = nt ? t1m : t0m;
            float v0 = (ta[0] + tb[0] + tc[0]) * 0.125f + __logf(fmaxf(wa.x, 1e-6f));
            float v1 = (ta[1] + tb[1] + tc[1]) * 0.125f + __logf(fmaxf(wa.y, 1e-6f));
            float v2 = (ta[2] + tb[2] + tc[2]) * 0.125f + __logf(fmaxf(wb.x, 1e-6f));
            float v3 = (ta[3] + tb[3] + tc[3]) * 0.125f + __logf(fmaxf(wb.y, 1e-6f));
            s[kb][j + 0] = v0; s[kb][j + 1] = v1;
            s[kb][j + 2] = v2; s[kb][j + 3] = v3;
            m0 = fmaxf(m0, fmaxf(v0, v1));
            m1 = fmaxf(m1, fmaxf(v2, v3));
        }
    }

    // prefetch V chunk 0 (overlaps reductions + exp)
    loadChunk(vhi, vlo, 0, 0);
    CP_COMMIT();

    // ================= max/sum reductions + exp =================
    m0 = fmaxf(m0, __shfl_xor_sync(0xffffffffu, m0, 1));
    m0 = fmaxf(m0, __shfl_xor_sync(0xffffffffu, m0, 2));
    m1 = fmaxf(m1, __shfl_xor_sync(0xffffffffu, m1, 1));
    m1 = fmaxf(m1, __shfl_xor_sync(0xffffffffu, m1, 2));
    if ((lane & 3) == 0) {
        pmaxs[rl0 * 8 + wq]       = m0;
        pmaxs[(rl0 + 8) * 8 + wq] = m1;
    }
    __syncthreads();
    {
        float fm0 = -1e30f, fm1 = -1e30f;
        #pragma unroll
        for (int i = 0; i < 8; i++) {
            fm0 = fmaxf(fm0, pmaxs[rl0 * 8 + i]);
            fm1 = fmaxf(fm1, pmaxs[(rl0 + 8) * 8 + i]);
        }
        m0 = fm0; m1 = fm1;
    }
    float sum0 = 0.f, sum1 = 0.f;
    #pragma unroll
    for (int kb = 0; kb < 8; kb++) {
        #pragma unroll
        for (int j = 0; j < 8; j++) {
            float e = __expf(s[kb][j] - ((j & 2) ? m1 : m0));
            s[kb][j] = e;
            if (j & 2) sum1 += e; else sum0 += e;
        }
    }
    sum0 += __shfl_xor_sync(0xffffffffu, sum0, 1);
    sum0 += __shfl_xor_sync(0xffffffffu, sum0, 2);
    sum1 += __shfl_xor_sync(0xffffffffu, sum1, 1);
    sum1 += __shfl_xor_sync(0xffffffffu, sum1, 2);
    if ((lane & 3) == 0) {
        psums[rl0 * 8 + wq]       = sum0;
        psums[(rl0 + 8) * 8 + wq] = sum1;
    }
    __syncthreads();
    float inv0, inv1;
    {
        float t0 = 0.f, t1 = 0.f;
        #pragma unroll
        for (int i = 0; i < 8; i++) {
            t0 += psums[rl0 * 8 + i];
            t1 += psums[(rl0 + 8) * 8 + i];
        }
        inv0 = 1.f / t0; inv1 = 1.f / t1;
    }

    // ================= P @ V with fused normalize/pack/mn-store ===============
    float* mrow0 = mn + grow0;
    float* mrow1 = mn + grow0 + (8 << 10);
    float accO[8][4];
    #pragma unroll
    for (int t = 0; t < 8; t++)
        #pragma unroll
        for (int j = 0; j < 4; j++) accO[t][j] = 0.f;

    for (int kb = 0; kb < 8; kb++) {
        CP_WAIT0();
        __syncthreads();
        if (kb < 7) {
            loadChunk(vhi, vlo, kb + 1, (kb + 1) & 1);
            CP_COMMIT();
        }

        // normalize chunk kb, write mn, pack in place
        #pragma unroll
        for (int nt = 0; nt < 2; nt++) {
            int col = kb * 128 + wq * 16 + nt * 8 + c2;
            int j = nt * 4;
            float p0 = s[kb][j + 0] * inv0;
            float p1 = s[kb][j + 1] * inv0;
            float p2 = s[kb][j + 2] * inv1;
            float p3 = s[kb][j + 3] * inv1;
            *(float2*)&mrow0[col] = make_float2(p0, p1);
            *(float2*)&mrow1[col] = make_float2(p2, p3);
            s[kb][j + 0] = __uint_as_float(packP(p0));
            s[kb][j + 1] = __uint_as_float(packP(p1));
            s[kb][j + 2] = __uint_as_float(packP(p2));
            s[kb][j + 3] = __uint_as_float(packP(p3));
        }

        // A-frags from packed P words
        uint32_t ah[4], al[4];
        {
            uint32_t w0 = __float_as_uint(s[kb][0]), w1 = __float_as_uint(s[kb][1]);
            uint32_t w2 = __float_as_uint(s[kb][2]), w3 = __float_as_uint(s[kb][3]);
            uint32_t w4 = __float_as_uint(s[kb][4]), w5 = __float_as_uint(s[kb][5]);
            uint32_t w6 = __float_as_uint(s[kb][6]), w7 = __float_as_uint(s[kb][7]);
            ah[0] = __byte_perm(w0, w1, 0x5410); al[0] = __byte_perm(w0, w1, 0x7632);
            ah[1] = __byte_perm(w2, w3, 0x5410); al[1] = __byte_perm(w2, w3, 0x7632);
            ah[2] = __byte_perm(w4, w5, 0x5410); al[2] = __byte_perm(w4, w5, 0x7632);
            ah[3] = __byte_perm(w6, w7, 0x5410); al[3] = __byte_perm(w6, w7, 0x7632);
        }

        const uint32_t vbase = sb + (kb & 1) * ATT_KVSZ;
        #pragma unroll
        for (int ng = 0; ng < 4; ng++) {
            uint32_t vaddr = vbase +
                ((uint32_t)((wq * 16 + (lane & 15)) * 72) +
                 ng * 16 + (lane >> 4) * 8) * 2;
            uint32_t bh[4], bl[4];
            ldsm_x4t(bh, vaddr);
            ldsm_x4t(bl, vaddr + ATT_LO);
            float* c0 = accO[ng * 2];
            float* c1 = accO[ng * 2 + 1];
            mma_bf16(c0, ah, bh[0], bh[1]);
            mma_bf16(c0, ah, bl[0], bl[1]);
            mma_bf16(c0, al, bh[0], bh[1]);
            mma_bf16(c1, ah, bh[2], bh[3]);
            mma_bf16(c1, ah, bl[2], bl[3]);
            mma_bf16(c1, al, bh[2], bh[3]);
        }
    }
    __syncthreads();   // V reads done; reuse KV region as reduction buffer

    // ---- 8-way k-slice reduction via smem ----
    float* red = (float*)smem;          // 16 slabs x 16x64 f32 = 64KB
    {
        float* slab = red + wid * 1024;
        #pragma unroll
        for (int t = 0; t < 8; t++) {
            int col = (t >> 1) * 16 + (t & 1) * 8 + c2;
            *(float2*)&slab[g * 64 + col]       = make_float2(accO[t][0], accO[t][1]);
            *(float2*)&slab[(g + 8) * 64 + col] = make_float2(accO[t][2], accO[t][3]);
        }
    }
    __syncthreads();
    {
        int row = tid >> 4;             // 0..31
        int c4  = (tid & 15) * 4;
        int h   = row >> 4, rl = row & 15;
        float4 v = make_float4(0.f, 0.f, 0.f, 0.f);
        #pragma unroll
        for (int w2 = 0; w2 < 8; w2++) {
            float4 p = *(float4*)&red[(h * 8 + w2) * 1024 + rl * 64 + c4];
            v.x += p.x; v.y += p.y; v.z += p.z; v.w += p.w;
        }
        float* dst = attnout + (size_t)(bb * NSEQ + q0 + row) * 512 + hh * 64 + c4;
        *(float4*)dst = v;
    }
}

// =============================================================================
extern "C" void kernel_launch(void* const* d_in, const int* in_sizes, int n_in,
                              void* d_out, int out_size)
{
    const float* queries = (const float*)d_in[0];
    const float* keys    = (const float*)d_in[1];
    const float* values  = (const float*)d_in[2];
    const float* relw    = (const float*)d_in[3];
    const float* Wq = (const float*)d_in[4];
    const float* bq = (const float*)d_in[5];
    const float* Wk = (const float*)d_in[6];
    const float* bk = (const float*)d_in[7];
    const float* Wv = (const float*)d_in[8];
    const float* bv = (const float*)d_in[9];
    const float* Wo = (const float*)d_in[10];
    const float* bo = (const float*)d_in[11];

    float* out_main = (float*)d_out;
    float* out_mn   = (float*)d_out + (size_t)BATCH * NSEQ * DM;

    __nv_bfloat16 *qhi, *qlo, *khi, *klo, *vhi, *vlo;
    float* gattn;
    cudaGetSymbolAddress((void**)&qhi, g_qhi);
    cudaGetSymbolAddress((void**)&qlo, g_qlo);
    cudaGetSymbolAddress((void**)&khi, g_khi);
    cudaGetSymbolAddress((void**)&klo, g_klo);
    cudaGetSymbolAddress((void**)&vhi, g_vhi);
    cudaGetSymbolAddress((void**)&vlo, g_vlo);
    cudaGetSymbolAddress((void**)&gattn, g_attn);

    cudaFuncSetAttribute(gemm_tc<0>, cudaFuncAttributeMaxDynamicSharedMemorySize, GEMM_SMEM);
    cudaFuncSetAttribute(gemm_tc<1>, cudaFuncAttributeMaxDynamicSharedMemorySize, GEMM_SMEM);
    cudaFuncSetAttribute(attn_tc, cudaFuncAttributeMaxDynamicSharedMemorySize, ATT_SMEM);

    dim3 ggrid(4, 128);

    gemm_tc<0><<<ggrid, 256, GEMM_SMEM>>>(queries, Wq, bq, nullptr, qhi, qlo);
    gemm_tc<0><<<ggrid, 256, GEMM_SMEM>>>(keys,    Wk, bk, nullptr, khi, klo);
    gemm_tc<0><<<ggrid, 256, GEMM_SMEM>>>(values,  Wv, bv, nullptr, vhi, vlo);

    attn_tc<<<dim3(32, NH, BATCH), 512, ATT_SMEM>>>(
        qhi, qlo, khi, klo, vhi, vlo, relw, out_mn, gattn);

    gemm_tc<1><<<ggrid, 256, GEMM_SMEM>>>(gattn, Wo, bo, out_main, nullptr, nullptr);
}

// round 9
// speedup vs baseline: 1.3683x; 1.0862x over previous
#include <cuda_runtime.h>
#include <cuda_bf16.h>
#include <cstdint>
#include <math.h>

#define BATCH 16
#define NSEQ  1024
#define NH    8
#define HD    64
#define DM    512

// ---------------- scratch (static device arrays; no allocation) ----------------
#define QKV_ELEMS (BATCH*NH*NSEQ*HD)
__device__ __nv_bfloat16 g_qhi[QKV_ELEMS];
__device__ __nv_bfloat16 g_qlo[QKV_ELEMS];
__device__ __nv_bfloat16 g_khi[QKV_ELEMS];
__device__ __nv_bfloat16 g_klo[QKV_ELEMS];
__device__ __nv_bfloat16 g_vhi[QKV_ELEMS];
__device__ __nv_bfloat16 g_vlo[QKV_ELEMS];
__device__ float g_attn[BATCH*NSEQ*DM];

// =============================================================================
// helpers
// =============================================================================
__device__ __forceinline__ uint32_t smem_u32(const void* p) {
    uint32_t a;
    asm("{ .reg .u64 t; cvta.to.shared.u64 t, %1; cvt.u32.u64 %0, t; }"
        : "=r"(a) : "l"(p));
    return a;
}
__device__ __forceinline__ void ldsm_x4(uint32_t* r, uint32_t addr) {
    asm volatile("ldmatrix.sync.aligned.m8n8.x4.shared.b16 {%0,%1,%2,%3}, [%4];"
        : "=r"(r[0]), "=r"(r[1]), "=r"(r[2]), "=r"(r[3]) : "r"(addr));
}
__device__ __forceinline__ void ldsm_x4t(uint32_t* r, uint32_t addr) {
    asm volatile("ldmatrix.sync.aligned.m8n8.x4.trans.shared.b16 {%0,%1,%2,%3}, [%4];"
        : "=r"(r[0]), "=r"(r[1]), "=r"(r[2]), "=r"(r[3]) : "r"(addr));
}
__device__ __forceinline__ void mma_bf16(float* c, const uint32_t* a,
                                         uint32_t b0, uint32_t b1) {
    asm volatile(
        "mma.sync.aligned.m16n8k16.row.col.f32.bf16.bf16.f32 "
        "{%0,%1,%2,%3}, {%4,%5,%6,%7}, {%8,%9}, {%0,%1,%2,%3};"
        : "+f"(c[0]), "+f"(c[1]), "+f"(c[2]), "+f"(c[3])
        : "r"(a[0]), "r"(a[1]), "r"(a[2]), "r"(a[3]), "r"(b0), "r"(b1));
}
__device__ __forceinline__ void cp16(uint32_t dst, const void* src) {
    asm volatile("cp.async.cg.shared.global [%0], [%1], 16;" :: "r"(dst), "l"(src));
}
#define CP_COMMIT() asm volatile("cp.async.commit_group;" ::: "memory")
#define CP_WAIT0()  asm volatile("cp.async.wait_group 0;" ::: "memory")
#define CP_WAIT1()  asm volatile("cp.async.wait_group 1;" ::: "memory")

__device__ __forceinline__ uint32_t pack_bf16_res(float a, float b, float& ra, float& rb) {
    __nv_bfloat16 ha = __float2bfloat16(a), hb = __float2bfloat16(b);
    ra = a - __bfloat162float(ha);
    rb = b - __bfloat162float(hb);
    __nv_bfloat162 p(ha, hb);
    return *reinterpret_cast<uint32_t*>(&p);
}
__device__ __forceinline__ uint32_t pack_bf16(float a, float b) {
    __nv_bfloat162 p(__float2bfloat16(a), __float2bfloat16(b));
    return *reinterpret_cast<uint32_t*>(&p);
}
// word: low16 = bf16 hi(p), high16 = bf16 lo-residual(p)
__device__ __forceinline__ uint32_t packP(float p) {
    __nv_bfloat16 hi = __float2bfloat16(p);
    __nv_bfloat16 lo = __float2bfloat16(p - __bfloat162float(hi));
    uint16_t hb = *reinterpret_cast<uint16_t*>(&hi);
    uint16_t lb = *reinterpret_cast<uint16_t*>(&lo);
    return (uint32_t)hb | ((uint32_t)lb << 16);
}

// =============================================================================
// Tensor-core (HMMA) GEMM body: C[16384,512] = X @ W + bias, bf16 split-3.
// MODE 0: write bf16 hi/lo pair scattered to [b,h,n,d]. MODE 1: fp32 row-major.
// =============================================================================
#define ASTRIDE 40
#define BSTRIDE 136
#define A_BYTES (128*ASTRIDE*2)
#define B_BYTES (32*BSTRIDE*2)
#define OFF_ALO A_BYTES
#define OFF_BHI (2*A_BYTES)
#define OFF_BLO (2*A_BYTES + B_BYTES)
#define GBUF    (2*A_BYTES + 2*B_BYTES)
#define GEMM_SMEM (2*GBUF)

template<int MODE>
__device__ __forceinline__ void gemm_body(
    const float* __restrict__ X, const float* __restrict__ W,
    const float* __restrict__ bias, float* __restrict__ out,
    __nv_bfloat16* __restrict__ ohi, __nv_bfloat16* __restrict__ olo,
    char* smem)
{
    const uint32_t sb = smem_u32(smem);
    const int tid  = threadIdx.x;
    const int wid  = tid >> 5, lane = tid & 31;
    const int wm   = wid >> 2;
    const int wn   = wid & 3;
    const int n0   = blockIdx.x * 128;
    const int m0   = blockIdx.y * 128;

    float acc[4][4][4];
    #pragma unroll
    for (int i = 0; i < 4; i++)
        #pragma unroll
        for (int j = 0; j < 4; j++)
            #pragma unroll
            for (int k = 0; k < 4; k++) acc[i][j][k] = 0.f;

    float4 ra[4], rb[4];

    auto gload = [&](int c) {
        const int k0 = c * 32;
        #pragma unroll
        for (int i = 0; i < 4; i++) {
            int idx = i * 256 + tid;
            int row = idx >> 3, col = (idx & 7) * 4;
            ra[i] = *(const float4*)&X[(size_t)(m0 + row) * 512 + k0 + col];
        }
        #pragma unroll
        for (int i = 0; i < 4; i++) {
            int idx = i * 256 + tid;
            int kk = idx >> 5, col = (idx & 31) * 4;
            rb[i] = *(const float4*)&W[(size_t)(k0 + kk) * 512 + n0 + col];
        }
    };

    auto cstore = [&](int buf) {
        char* bp = smem + buf * GBUF;
        #pragma unroll
        for (int i = 0; i < 4; i++) {
            int idx = i * 256 + tid;
            int row = idx >> 3, col = (idx & 7) * 4;
            float r0, r1, r2, r3;
            uint2 hi, lo;
            hi.x = pack_bf16_res(ra[i].x, ra[i].y, r0, r1);
            hi.y = pack_bf16_res(ra[i].z, ra[i].w, r2, r3);
            lo.x = pack_bf16(r0, r1);
            lo.y = pack_bf16(r2, r3);
            uint32_t off = (uint32_t)(row * ASTRIDE + col) * 2;
            *(uint2*)(bp + off)           = hi;
            *(uint2*)(bp + OFF_ALO + off) = lo;
        }
        #pragma unroll
        for (int i = 0; i < 4; i++) {
            int idx = i * 256 + tid;
            int kk = idx >> 5, col = (idx & 31) * 4;
            float r0, r1, r2, r3;
            uint2 hi, lo;
            hi.x = pack_bf16_res(rb[i].x, rb[i].y, r0, r1);
            hi.y = pack_bf16_res(rb[i].z, rb[i].w, r2, r3);
            lo.x = pack_bf16(r0, r1);
            lo.y = pack_bf16(r2, r3);
            uint32_t off = (uint32_t)(kk * BSTRIDE + col) * 2;
            *(uint2*)(bp + OFF_BHI + off) = hi;
            *(uint2*)(bp + OFF_BLO + off) = lo;
        }
    };

    const uint32_t aLane = (uint32_t)((wm * 64 + (lane & 15)) * ASTRIDE + (lane >> 4) * 8) * 2;
    const uint32_t bLane = (uint32_t)((lane & 15) * BSTRIDE + wn * 32 + (lane >> 4) * 8) * 2;

    auto compute = [&](int buf) {
        const uint32_t base = sb + buf * GBUF;
        #pragma unroll
        for (int ks = 0; ks < 2; ks++) {
            uint32_t ah[4][4], al[4][4], bh[2][4], bl[2][4];
            #pragma unroll
            for (int mt = 0; mt < 4; mt++) {
                uint32_t ad = base + aLane + (uint32_t)(mt * 16 * ASTRIDE + ks * 16) * 2;
                ldsm_x4(ah[mt], ad);
                ldsm_x4(al[mt], ad + OFF_ALO);
            }
            #pragma unroll
            for (int nt = 0; nt < 2; nt++) {
                uint32_t bd = base + OFF_BHI + bLane +
                              (uint32_t)(ks * 16 * BSTRIDE + nt * 16) * 2;
                ldsm_x4t(bh[nt], bd);
                ldsm_x4t(bl[nt], bd + B_BYTES);
            }
            #pragma unroll
            for (int mt = 0; mt < 4; mt++) {
                #pragma unroll
                for (int n8 = 0; n8 < 4; n8++) {
                    const int nt = n8 >> 1, hf = (n8 & 1) * 2;
                    float* c = acc[mt][n8];
                    mma_bf16(c, ah[mt], bh[nt][hf], bh[nt][hf + 1]);
                    mma_bf16(c, ah[mt], bl[nt][hf], bl[nt][hf + 1]);
                    mma_bf16(c, al[mt], bh[nt][hf], bh[nt][hf + 1]);
                }
            }
        }
    };

    gload(0);
    cstore(0);
    __syncthreads();
    for (int c = 0; c < 16; c++) {
        if (c < 15) gload(c + 1);
        compute(c & 1);
        if (c < 15) {
            cstore((c + 1) & 1);
            __syncthreads();
        }
    }

    const int gid = lane >> 2;
    const int cid = (lane & 3) * 2;
    #pragma unroll
    for (int mt = 0; mt < 4; mt++) {
        #pragma unroll
        for (int n8 = 0; n8 < 4; n8++) {
            int row = m0 + wm * 64 + mt * 16 + gid;
            int col = n0 + wn * 32 + n8 * 8 + cid;
            float b0 = __ldg(&bias[col]), b1 = __ldg(&bias[col + 1]);
            float2 v0 = make_float2(acc[mt][n8][0] + b0, acc[mt][n8][1] + b1);
            float2 v1 = make_float2(acc[mt][n8][2] + b0, acc[mt][n8][3] + b1);
            if (MODE == 0) {
                int h = col >> 6, d = col & 63;
                #pragma unroll
                for (int rr = 0; rr < 2; rr++) {
                    int r = row + rr * 8;
                    float2 v = rr ? v1 : v0;
                    int bi = r >> 10, ni = r & 1023;
                    size_t idx = (size_t)(((bi * NH + h) << 10) + ni) * 64 + d;
                    float e0, e1;
                    uint32_t hi = pack_bf16_res(v.x, v.y, e0, e1);
                    uint32_t lo = pack_bf16(e0, e1);
                    *(uint32_t*)&ohi[idx] = hi;
                    *(uint32_t*)&olo[idx] = lo;
                }
            } else {
                *(float2*)&out[(size_t)row * 512 + col]       = v0;
                *(float2*)&out[(size_t)(row + 8) * 512 + col] = v1;
            }
        }
    }
}

// fused QKV projection: blockIdx.z selects (X, W, bias, dst)
__global__ __launch_bounds__(256, 1) void gemm_qkv(
    const float* xq, const float* xk, const float* xv,
    const float* wq, const float* wk, const float* wv,
    const float* bq, const float* bk, const float* bv,
    __nv_bfloat16* qh, __nv_bfloat16* ql,
    __nv_bfloat16* kh, __nv_bfloat16* kl,
    __nv_bfloat16* vh, __nv_bfloat16* vl)
{
    extern __shared__ char smem[];
    const int z = blockIdx.z;
    const float* X = (z == 0) ? xq : (z == 1) ? xk : xv;
    const float* W = (z == 0) ? wq : (z == 1) ? wk : wv;
    const float* B = (z == 0) ? bq : (z == 1) ? bk : bv;
    __nv_bfloat16* oh = (z == 0) ? qh : (z == 1) ? kh : vh;
    __nv_bfloat16* ol = (z == 0) ? ql : (z == 1) ? kl : vl;
    gemm_body<0>(X, W, B, nullptr, oh, ol, smem);
}

__global__ __launch_bounds__(256, 1) void gemm_out(
    const float* __restrict__ X, const float* __restrict__ W,
    const float* __restrict__ bias, float* __restrict__ out)
{
    extern __shared__ char smem[];
    gemm_body<1>(X, W, bias, out, nullptr, nullptr, smem);
}

// =============================================================================
// Register-resident fused attention, triple-buffered 16-chunk pipeline:
//  chunks 0..7 = K (+ gw log-bias chunks), 8..15 = V; buffers = chunk%3;
//  wait_group 1 -> each chunk's loads get ~2 compute-phases to land.
// 512 threads / 16 warps, 32 q-rows/CTA.
// =============================================================================
#define KVSTR   144
#define ATT_KVSZ 36864           // 128 rows * 144B * 2 planes
#define ATT_LO   18432
#define ATT_Q    (3*ATT_KVSZ)    // 110592
#define ATT_QLO  4608
#define ATT_W    (ATT_Q + 9216)  // 119808; w chunk: 32 rows x 132 floats
#define WSTR     132
#define ATT_WSZ  (32*WSTR*4)     // 16896
#define ATT_PM   (ATT_W + 3*ATT_WSZ)   // 170496
#define ATT_PS   (ATT_PM + 1024)
#define ATT_SMEM (ATT_PS + 1024)       // 172544

__global__ __launch_bounds__(512, 1) void attn_tc(
    const __nv_bfloat16* __restrict__ qhi, const __nv_bfloat16* __restrict__ qlo,
    const __nv_bfloat16* __restrict__ khi, const __nv_bfloat16* __restrict__ klo,
    const __nv_bfloat16* __restrict__ vhi, const __nv_bfloat16* __restrict__ vlo,
    const float* __restrict__ gw, float* __restrict__ mn,
    float* __restrict__ attnout)
{
    extern __shared__ char smem[];
    const uint32_t sb = smem_u32(smem);
    float* pmaxs = (float*)(smem + ATT_PM);
    float* psums = (float*)(smem + ATT_PS);

    const int tid = threadIdx.x, wid = tid >> 5, lane = tid & 31;
    const int wmq = wid >> 3;          // m half (16 rows)
    const int wq  = wid & 7;           // 16-col slice of each 128 chunk
    const int q0 = blockIdx.x * 32, hh = blockIdx.y, bb = blockIdx.z;
    const size_t bhBase = (size_t)(bb * NH + hh) * NSEQ;

    // K/V chunk loader: 128 rows x 64 cols, hi+lo planes
    auto loadChunk = [&](const __nv_bfloat16* hi, const __nv_bfloat16* lo,
                         int kb, int buf) {
        uint32_t dst = sb + buf * ATT_KVSZ;
        const __nv_bfloat16* sh = hi + (bhBase + kb * 128) * 64;
        const __nv_bfloat16* sl = lo + (bhBase + kb * 128) * 64;
        #pragma unroll
        for (int i = 0; i < 2; i++) {
            int idx = i * 512 + tid;
            int row = idx >> 3, col = (idx & 7) * 8;
            uint32_t d = dst + row * KVSTR + col * 2;
            cp16(d,          sh + row * 64 + col);
            cp16(d + ATT_LO, sl + row * 64 + col);
        }
    };
    // w chunk loader: 32 q-rows x 128 cols fp32
    auto loadW = [&](int kb, int buf) {
        uint32_t dst = sb + ATT_W + buf * ATT_WSZ;
        const float* src = gw + ((bhBase + q0) << 10) + kb * 128;
        #pragma unroll
        for (int i = 0; i < 2; i++) {
            int idx = i * 512 + tid;
            int row = idx >> 5, col = (idx & 31) * 4;
            cp16(dst + (uint32_t)(row * WSTR + col) * 4,
                 src + ((size_t)row << 10) + col);
        }
    };

    // ---- prologue: chunks 0 and 1 in flight ----
    loadChunk(khi, klo, 0, 0);
    loadW(0, 0);
    CP_COMMIT();
    loadChunk(khi, klo, 1, 1);
    loadW(1, 1);
    CP_COMMIT();

    // ---- stage Q tile (32x64 hi/lo) ----
    {
        int pos = tid & 255;
        int row = pos >> 3, col = (pos & 7) * 8;
        size_t g = (bhBase + q0 + row) * 64 + col;
        if (tid < 256)
            *(uint4*)(smem + ATT_Q + row * KVSTR + col * 2)           = *(const uint4*)&qhi[g];
        else
            *(uint4*)(smem + ATT_Q + ATT_QLO + row * KVSTR + col * 2) = *(const uint4*)&qlo[g];
    }
    __syncthreads();

    // ---- Q fragments (m16 x k64 for this m-half) ----
    uint32_t aQh[4][4], aQl[4][4];
    {
        const uint32_t qaddr = sb + ATT_Q +
            ((uint32_t)((wmq * 16 + (lane & 15)) * 72) + (lane >> 4) * 8) * 2;
        #pragma unroll
        for (int ks = 0; ks < 4; ks++) {
            ldsm_x4(aQh[ks], qaddr + ks * 32);
            ldsm_x4(aQl[ks], qaddr + ks * 32 + ATT_QLO);
        }
    }

    const int g   = lane >> 2;
    const int c2  = (lane & 3) * 2;
    const int rl0 = wmq * 16 + g;              // CTA-local rows rl0, rl0+8
    const size_t grow0 = (bhBase + q0 + rl0) << 10;

    // ================= QK^T + fused log-bias + running max ====================
    float s[8][8];
    float m0 = -1e30f, m1 = -1e30f;
    for (int kb = 0; kb < 8; kb++) {
        CP_WAIT1();
        __syncthreads();
        {
            int nc = kb + 2;            // next chunk to stage (2..9)
            if (nc < 8) {
                loadChunk(khi, klo, nc, nc % 3);
                loadW(nc, nc % 3);
            } else {
                loadChunk(vhi, vlo, nc - 8, nc % 3);   // V chunks 0,1
            }
            CP_COMMIT();
        }

        const uint32_t baddr = sb + (kb % 3) * ATT_KVSZ +
            ((uint32_t)((wq * 16 + (lane & 15)) * 72) + (lane >> 4) * 8) * 2;

        // 3 independent chains per n8 tile (split terms), depth 4 each
        float t0h[4] = {0,0,0,0}, t0l[4] = {0,0,0,0}, t0m[4] = {0,0,0,0};
        float t1h[4] = {0,0,0,0}, t1l[4] = {0,0,0,0}, t1m[4] = {0,0,0,0};
        #pragma unroll
        for (int ks = 0; ks < 4; ks++) {
            uint32_t bh[4], bl[4];
            ldsm_x4(bh, baddr + ks * 32);
            ldsm_x4(bl, baddr + ks * 32 + ATT_LO);
            mma_bf16(t0h, aQh[ks], bh[0], bh[2]);
            mma_bf16(t0l, aQh[ks], bl[0], bl[2]);
            mma_bf16(t0m, aQl[ks], bh[0], bh[2]);
            mma_bf16(t1h, aQh[ks], bh[1], bh[3]);
            mma_bf16(t1l, aQh[ks], bl[1], bl[3]);
            mma_bf16(t1m, aQl[ks], bh[1], bh[3]);
        }

        // merge + fused scale/log-bias from smem W buffer
        const float* wsm = (const float*)(smem + ATT_W + (kb % 3) * ATT_WSZ);
        #pragma unroll
        for (int nt = 0; nt < 2; nt++) {
            int wcol = wq * 16 + nt * 8 + c2;
            float2 wa = *(const float2*)&wsm[rl0 * WSTR + wcol];
            float2 wb = *(const float2*)&wsm[(rl0 + 8) * WSTR + wcol];
            int j = nt * 4;
            float* ta = nt ? t1h : t0h;
            float* tb = nt ? t1l : t0l;
            float* tc = nt ? t1m : t0m;
            float v0 = (ta[0] + tb[0] + tc[0]) * 0.125f + __logf(fmaxf(wa.x, 1e-6f));
            float v1 = (ta[1] + tb[1] + tc[1]) * 0.125f + __logf(fmaxf(wa.y, 1e-6f));
            float v2 = (ta[2] + tb[2] + tc[2]) * 0.125f + __logf(fmaxf(wb.x, 1e-6f));
            float v3 = (ta[3] + tb[3] + tc[3]) * 0.125f + __logf(fmaxf(wb.y, 1e-6f));
            s[kb][j + 0] = v0; s[kb][j + 1] = v1;
            s[kb][j + 2] = v2; s[kb][j + 3] = v3;
            m0 = fmaxf(m0, fmaxf(v0, v1));
            m1 = fmaxf(m1, fmaxf(v2, v3));
        }
    }

    // ================= max/sum reductions + exp (V0/V1 landing meanwhile) =====
    m0 = fmaxf(m0, __shfl_xor_sync(0xffffffffu, m0, 1));
    m0 = fmaxf(m0, __shfl_xor_sync(0xffffffffu, m0, 2));
    m1 = fmaxf(m1, __shfl_xor_sync(0xffffffffu, m1, 1));
    m1 = fmaxf(m1, __shfl_xor_sync(0xffffffffu, m1, 2));
    if ((lane & 3) == 0) {
        pmaxs[rl0 * 8 + wq]       = m0;
        pmaxs[(rl0 + 8) * 8 + wq] = m1;
    }
    __syncthreads();
    {
        float fm0 = -1e30f, fm1 = -1e30f;
        #pragma unroll
        for (int i = 0; i < 8; i++) {
            fm0 = fmaxf(fm0, pmaxs[rl0 * 8 + i]);
            fm1 = fmaxf(fm1, pmaxs[(rl0 + 8) * 8 + i]);
        }
        m0 = fm0; m1 = fm1;
    }
    float sum0 = 0.f, sum1 = 0.f;
    #pragma unroll
    for (int kb = 0; kb < 8; kb++) {
        #pragma unroll
        for (int j = 0; j < 8; j++) {
            float e = __expf(s[kb][j] - ((j & 2) ? m1 : m0));
            s[kb][j] = e;
            if (j & 2) sum1 += e; else sum0 += e;
        }
    }
    sum0 += __shfl_xor_sync(0xffffffffu, sum0, 1);
    sum0 += __shfl_xor_sync(0xffffffffu, sum0, 2);
    sum1 += __shfl_xor_sync(0xffffffffu, sum1, 1);
    sum1 += __shfl_xor_sync(0xffffffffu, sum1, 2);
    if ((lane & 3) == 0) {
        psums[rl0 * 8 + wq]       = sum0;
        psums[(rl0 + 8) * 8 + wq] = sum1;
    }
    __syncthreads();
    float inv0, inv1;
    {
        float t0 = 0.f, t1 = 0.f;
        #pragma unroll
        for (int i = 0; i < 8; i++) {
            t0 += psums[rl0 * 8 + i];
            t1 += psums[(rl0 + 8) * 8 + i];
        }
        inv0 = 1.f / t0; inv1 = 1.f / t1;
    }

    // ================= P @ V with fused normalize/pack/mn-store ===============
    float* mrow0 = mn + grow0;
    float* mrow1 = mn + grow0 + (8 << 10);
    float accO[8][4];
    #pragma unroll
    for (int t = 0; t < 8; t++)
        #pragma unroll
        for (int j = 0; j < 4; j++) accO[t][j] = 0.f;

    for (int kb = 0; kb < 8; kb++) {
        const int c = kb + 8;
        CP_WAIT1();
        __syncthreads();
        {
            int nc = c + 2;
            if (nc < 16) loadChunk(vhi, vlo, nc - 8, nc % 3);
            CP_COMMIT();               // empty groups keep bookkeeping aligned
        }

        // normalize chunk kb, write mn, pack in place
        #pragma unroll
        for (int nt = 0; nt < 2; nt++) {
            int col = kb * 128 + wq * 16 + nt * 8 + c2;
            int j = nt * 4;
            float p0 = s[kb][j + 0] * inv0;
            float p1 = s[kb][j + 1] * inv0;
            float p2 = s[kb][j + 2] * inv1;
            float p3 = s[kb][j + 3] * inv1;
            *(float2*)&mrow0[col] = make_float2(p0, p1);
            *(float2*)&mrow1[col] = make_float2(p2, p3);
            s[kb][j + 0] = __uint_as_float(packP(p0));
            s[kb][j + 1] = __uint_as_float(packP(p1));
            s[kb][j + 2] = __uint_as_float(packP(p2));
            s[kb][j + 3] = __uint_as_float(packP(p3));
        }

        // A-frags from packed P words
        uint32_t ah[4], al[4];
        {
            uint32_t w0 = __float_as_uint(s[kb][0]), w1 = __float_as_uint(s[kb][1]);
            uint32_t w2 = __float_as_uint(s[kb][2]), w3 = __float_as_uint(s[kb][3]);
            uint32_t w4 = __float_as_uint(s[kb][4]), w5 = __float_as_uint(s[kb][5]);
            uint32_t w6 = __float_as_uint(s[kb][6]), w7 = __float_as_uint(s[kb][7]);
            ah[0] = __byte_perm(w0, w1, 0x5410); al[0] = __byte_perm(w0, w1, 0x7632);
            ah[1] = __byte_perm(w2, w3, 0x5410); al[1] = __byte_perm(w2, w3, 0x7632);
            ah[2] = __byte_perm(w4, w5, 0x5410); al[2] = __byte_perm(w4, w5, 0x7632);
            ah[3] = __byte_perm(w6, w7, 0x5410); al[3] = __byte_perm(w6, w7, 0x7632);
        }

        const uint32_t vbase = sb + (c % 3) * ATT_KVSZ;
        #pragma unroll
        for (int ng = 0; ng < 4; ng++) {
            uint32_t vaddr = vbase +
                ((uint32_t)((wq * 16 + (lane & 15)) * 72) +
                 ng * 16 + (lane >> 4) * 8) * 2;
            uint32_t bh[4], bl[4];
            ldsm_x4t(bh, vaddr);
            ldsm_x4t(bl, vaddr + ATT_LO);
            float* c0 = accO[ng * 2];
            float* c1 = accO[ng * 2 + 1];
            mma_bf16(c0, ah, bh[0], bh[1]);
            mma_bf16(c0, ah, bl[0], bl[1]);
            mma_bf16(c0, al, bh[0], bh[1]);
            mma_bf16(c1, ah, bh[2], bh[3]);
            mma_bf16(c1, ah, bl[2], bl[3]);
            mma_bf16(c1, al, bh[2], bh[3]);
        }
    }
    __syncthreads();   // V reads done; reuse KV region as reduction buffer

    // ---- 8-way k-slice reduction via smem ----
    float* red = (float*)smem;          // 16 slabs x 16x64 f32 = 64KB
    {
        float* slab = red + wid * 1024;
        #pragma unroll
        for (int t = 0; t < 8; t++) {
            int col = (t >> 1) * 16 + (t & 1) * 8 + c2;
            *(float2*)&slab[g * 64 + col]       = make_float2(accO[t][0], accO[t][1]);
            *(float2*)&slab[(g + 8) * 64 + col] = make_float2(accO[t][2], accO[t][3]);
        }
    }
    __syncthreads();
    {
        int row = tid >> 4;             // 0..31
        int c4  = (tid & 15) * 4;
        int h   = row >> 4, rl = row & 15;
        float4 v = make_float4(0.f, 0.f, 0.f, 0.f);
        #pragma unroll
        for (int w2 = 0; w2 < 8; w2++) {
            float4 p = *(float4*)&red[(h * 8 + w2) * 1024 + rl * 64 + c4];
            v.x += p.x; v.y += p.y; v.z += p.z; v.w += p.w;
        }
        float* dst = attnout + (size_t)(bb * NSEQ + q0 + row) * 512 + hh * 64 + c4;
        *(float4*)dst = v;
    }
}

// =============================================================================
extern "C" void kernel_launch(void* const* d_in, const int* in_sizes, int n_in,
                              void* d_out, int out_size)
{
    const float* queries = (const float*)d_in[0];
    const float* keys    = (const float*)d_in[1];
    const float* values  = (const float*)d_in[2];
    const float* relw    = (const float*)d_in[3];
    const float* Wq = (const float*)d_in[4];
    const float* bq = (const float*)d_in[5];
    const float* Wk = (const float*)d_in[6];
    const float* bk = (const float*)d_in[7];
    const float* Wv = (const float*)d_in[8];
    const float* bv = (const float*)d_in[9];
    const float* Wo = (const float*)d_in[10];
    const float* bo = (const float*)d_in[11];

    float* out_main = (float*)d_out;
    float* out_mn   = (float*)d_out + (size_t)BATCH * NSEQ * DM;

    __nv_bfloat16 *qhi, *qlo, *khi, *klo, *vhi, *vlo;
    float* gattn;
    cudaGetSymbolAddress((void**)&qhi, g_qhi);
    cudaGetSymbolAddress((void**)&qlo, g_qlo);
    cudaGetSymbolAddress((void**)&khi, g_khi);
    cudaGetSymbolAddress((void**)&klo, g_klo);
    cudaGetSymbolAddress((void**)&vhi, g_vhi);
    cudaGetSymbolAddress((void**)&vlo, g_vlo);
    cudaGetSymbolAddress((void**)&gattn, g_attn);

    cudaFuncSetAttribute(gemm_qkv, cudaFuncAttributeMaxDynamicSharedMemorySize, GEMM_SMEM);
    cudaFuncSetAttribute(gemm_out, cudaFuncAttributeMaxDynamicSharedMemorySize, GEMM_SMEM);
    cudaFuncSetAttribute(attn_tc, cudaFuncAttributeMaxDynamicSharedMemorySize, ATT_SMEM);

    gemm_qkv<<<dim3(4, 128, 3), 256, GEMM_SMEM>>>(
        queries, keys, values, Wq, Wk, Wv, bq, bk, bv,
        qhi, qlo, khi, klo, vhi, vlo);

    attn_tc<<<dim3(32, NH, BATCH), 512, ATT_SMEM>>>(
        qhi, qlo, khi, klo, vhi, vlo, relw, out_mn, gattn);

    gemm_out<<<dim3(4, 128), 256, GEMM_SMEM>>>(gattn, Wo, bo, out_main);
}

// round 10
// speedup vs baseline: 1.4461x; 1.0569x over previous
#include <cuda_runtime.h>
#include <cuda_bf16.h>
#include <cstdint>
#include <math.h>

#define BATCH 16
#define NSEQ  1024
#define NH    8
#define HD    64
#define DM    512

// ---------------- scratch (static device arrays; no allocation) ----------------
#define QKV_ELEMS (BATCH*NH*NSEQ*HD)
__device__ __nv_bfloat16 g_qhi[QKV_ELEMS];
__device__ __nv_bfloat16 g_qlo[QKV_ELEMS];
__device__ __nv_bfloat16 g_khi[QKV_ELEMS];
__device__ __nv_bfloat16 g_klo[QKV_ELEMS];
__device__ __nv_bfloat16 g_vhi[QKV_ELEMS];
__device__ __nv_bfloat16 g_vlo[QKV_ELEMS];
__device__ float g_attn[BATCH*NSEQ*DM];
#define WMAT (512*512)
__device__ __nv_bfloat16 g_whi[4*WMAT];   // Wq, Wk, Wv, Wo hi planes
__device__ __nv_bfloat16 g_wlo[4*WMAT];

// =============================================================================
// helpers
// =============================================================================
__device__ __forceinline__ uint32_t smem_u32(const void* p) {
    uint32_t a;
    asm("{ .reg .u64 t; cvta.to.shared.u64 t, %1; cvt.u32.u64 %0, t; }"
        : "=r"(a) : "l"(p));
    return a;
}
__device__ __forceinline__ void ldsm_x4(uint32_t* r, uint32_t addr) {
    asm volatile("ldmatrix.sync.aligned.m8n8.x4.shared.b16 {%0,%1,%2,%3}, [%4];"
        : "=r"(r[0]), "=r"(r[1]), "=r"(r[2]), "=r"(r[3]) : "r"(addr));
}
__device__ __forceinline__ void ldsm_x4t(uint32_t* r, uint32_t addr) {
    asm volatile("ldmatrix.sync.aligned.m8n8.x4.trans.shared.b16 {%0,%1,%2,%3}, [%4];"
        : "=r"(r[0]), "=r"(r[1]), "=r"(r[2]), "=r"(r[3]) : "r"(addr));
}
__device__ __forceinline__ void mma_bf16(float* c, const uint32_t* a,
                                         uint32_t b0, uint32_t b1) {
    asm volatile(
        "mma.sync.aligned.m16n8k16.row.col.f32.bf16.bf16.f32 "
        "{%0,%1,%2,%3}, {%4,%5,%6,%7}, {%8,%9}, {%0,%1,%2,%3};"
        : "+f"(c[0]), "+f"(c[1]), "+f"(c[2]), "+f"(c[3])
        : "r"(a[0]), "r"(a[1]), "r"(a[2]), "r"(a[3]), "r"(b0), "r"(b1));
}
__device__ __forceinline__ void cp16(uint32_t dst, const void* src) {
    asm volatile("cp.async.cg.shared.global [%0], [%1], 16;" :: "r"(dst), "l"(src));
}
#define CP_COMMIT() asm volatile("cp.async.commit_group;" ::: "memory")
#define CP_WAIT0()  asm volatile("cp.async.wait_group 0;" ::: "memory")
#define CP_WAIT1()  asm volatile("cp.async.wait_group 1;" ::: "memory")

__device__ __forceinline__ uint32_t pack_bf16_res(float a, float b, float& ra, float& rb) {
    __nv_bfloat16 ha = __float2bfloat16(a), hb = __float2bfloat16(b);
    ra = a - __bfloat162float(ha);
    rb = b - __bfloat162float(hb);
    __nv_bfloat162 p(ha, hb);
    return *reinterpret_cast<uint32_t*>(&p);
}
__device__ __forceinline__ uint32_t pack_bf16(float a, float b) {
    __nv_bfloat162 p(__float2bfloat16(a), __float2bfloat16(b));
    return *reinterpret_cast<uint32_t*>(&p);
}
// word: low16 = bf16 hi(p), high16 = bf16 lo-residual(p)
__device__ __forceinline__ uint32_t packP(float p) {
    __nv_bfloat16 hi = __float2bfloat16(p);
    __nv_bfloat16 lo = __float2bfloat16(p - __bfloat162float(hi));
    uint16_t hb = *reinterpret_cast<uint16_t*>(&hi);
    uint16_t lb = *reinterpret_cast<uint16_t*>(&lo);
    return (uint32_t)hb | ((uint32_t)lb << 16);
}

// =============================================================================
// Weight pre-conversion: fp32 [512,512] -> bf16 hi/lo planes (once, all 4 mats)
// =============================================================================
__global__ __launch_bounds__(256) void conv_w(
    const float* w0, const float* w1, const float* w2, const float* w3,
    __nv_bfloat16* hi, __nv_bfloat16* lo)
{
    const int m = blockIdx.y;
    const float* w = (m == 0) ? w0 : (m == 1) ? w1 : (m == 2) ? w2 : w3;
    int idx = (blockIdx.x * 256 + threadIdx.x) * 4;
    float4 f = *(const float4*)&w[idx];
    float r0, r1, r2, r3;
    uint2 h, l;
    h.x = pack_bf16_res(f.x, f.y, r0, r1);
    h.y = pack_bf16_res(f.z, f.w, r2, r3);
    l.x = pack_bf16(r0, r1);
    l.y = pack_bf16(r2, r3);
    *(uint2*)&hi[m * WMAT + idx] = h;
    *(uint2*)&lo[m * WMAT + idx] = l;
}

// =============================================================================
// Tensor-core (HMMA) GEMM body: C[16384,512] = X @ W + bias, bf16 split-3.
// A: fp32 LDG -> convert -> STS (double-buffered via regs)
// B: pre-converted bf16 planes via cp.async (no convert, no reg staging)
// MODE 0: write bf16 hi/lo pair scattered to [b,h,n,d]. MODE 1: fp32 row-major.
// =============================================================================
#define ASTRIDE 40
#define BSTRIDE 136
#define A_BYTES (128*ASTRIDE*2)        // 10240
#define B_PLANE (32*BSTRIDE*2)         // 8704
#define OFF_ALO A_BYTES
#define OFF_BHI (2*A_BYTES)            // 20480
#define OFF_BLO (OFF_BHI + B_PLANE)    // 29184
#define GBUF    (OFF_BHI + 2*B_PLANE)  // 37888
#define GEMM_SMEM (2*GBUF)             // 75776

template<int MODE>
__device__ __forceinline__ void gemm_body(
    const float* __restrict__ X,
    const __nv_bfloat16* __restrict__ Whi, const __nv_bfloat16* __restrict__ Wlo,
    const float* __restrict__ bias, float* __restrict__ out,
    __nv_bfloat16* __restrict__ ohi, __nv_bfloat16* __restrict__ olo,
    char* smem)
{
    const uint32_t sb = smem_u32(smem);
    const int tid  = threadIdx.x;
    const int wid  = tid >> 5, lane = tid & 31;
    const int wm   = wid >> 2;
    const int wn   = wid & 3;
    const int n0   = blockIdx.x * 128;
    const int m0   = blockIdx.y * 128;

    float acc[4][4][4];
    #pragma unroll
    for (int i = 0; i < 4; i++)
        #pragma unroll
        for (int j = 0; j < 4; j++)
            #pragma unroll
            for (int k = 0; k < 4; k++) acc[i][j][k] = 0.f;

    float4 ra[4];

    auto gload = [&](int c) {
        const int k0 = c * 32;
        #pragma unroll
        for (int i = 0; i < 4; i++) {
            int idx = i * 256 + tid;
            int row = idx >> 3, col = (idx & 7) * 4;
            ra[i] = *(const float4*)&X[(size_t)(m0 + row) * 512 + k0 + col];
        }
    };

    auto bload = [&](int c, int buf) {
        const int k0 = c * 32;
        uint32_t dst = sb + buf * GBUF + OFF_BHI;
        const __nv_bfloat16* sh = Whi + (size_t)k0 * 512 + n0;
        const __nv_bfloat16* sl = Wlo + (size_t)k0 * 512 + n0;
        #pragma unroll
        for (int i = 0; i < 2; i++) {
            int idx = i * 256 + tid;
            int row = idx >> 4, col8 = (idx & 15) * 8;
            uint32_t d = dst + (uint32_t)(row * BSTRIDE + col8) * 2;
            cp16(d,               sh + row * 512 + col8);
            cp16(d + B_PLANE,     sl + row * 512 + col8);
        }
    };

    auto cstore = [&](int buf) {
        char* bp = smem + buf * GBUF;
        #pragma unroll
        for (int i = 0; i < 4; i++) {
            int idx = i * 256 + tid;
            int row = idx >> 3, col = (idx & 7) * 4;
            float r0, r1, r2, r3;
            uint2 hi, lo;
            hi.x = pack_bf16_res(ra[i].x, ra[i].y, r0, r1);
            hi.y = pack_bf16_res(ra[i].z, ra[i].w, r2, r3);
            lo.x = pack_bf16(r0, r1);
            lo.y = pack_bf16(r2, r3);
            uint32_t off = (uint32_t)(row * ASTRIDE + col) * 2;
            *(uint2*)(bp + off)           = hi;
            *(uint2*)(bp + OFF_ALO + off) = lo;
        }
    };

    const uint32_t aLane = (uint32_t)((wm * 64 + (lane & 15)) * ASTRIDE + (lane >> 4) * 8) * 2;
    const uint32_t bLane = (uint32_t)((lane & 15) * BSTRIDE + wn * 32 + (lane >> 4) * 8) * 2;

    auto compute = [&](int buf) {
        const uint32_t base = sb + buf * GBUF;
        #pragma unroll
        for (int ks = 0; ks < 2; ks++) {
            uint32_t ah[4][4], al[4][4], bh[2][4], bl[2][4];
            #pragma unroll
            for (int mt = 0; mt < 4; mt++) {
                uint32_t ad = base + aLane + (uint32_t)(mt * 16 * ASTRIDE + ks * 16) * 2;
                ldsm_x4(ah[mt], ad);
                ldsm_x4(al[mt], ad + OFF_ALO);
            }
            #pragma unroll
            for (int nt = 0; nt < 2; nt++) {
                uint32_t bd = base + OFF_BHI + bLane +
                              (uint32_t)(ks * 16 * BSTRIDE + nt * 16) * 2;
                ldsm_x4t(bh[nt], bd);
                ldsm_x4t(bl[nt], bd + B_PLANE);
            }
            #pragma unroll
            for (int mt = 0; mt < 4; mt++) {
                #pragma unroll
                for (int n8 = 0; n8 < 4; n8++) {
                    const int nt = n8 >> 1, hf = (n8 & 1) * 2;
                    float* c = acc[mt][n8];
                    mma_bf16(c, ah[mt], bh[nt][hf], bh[nt][hf + 1]);
                    mma_bf16(c, ah[mt], bl[nt][hf], bl[nt][hf + 1]);
                    mma_bf16(c, al[mt], bh[nt][hf], bh[nt][hf + 1]);
                }
            }
        }
    };

    gload(0);
    bload(0, 0);
    CP_COMMIT();
    cstore(0);
    CP_WAIT0();
    __syncthreads();
    for (int c = 0; c < 16; c++) {
        if (c < 15) {
            bload(c + 1, (c + 1) & 1);
            CP_COMMIT();
            gload(c + 1);
        }
        compute(c & 1);
        if (c < 15) {
            cstore((c + 1) & 1);
            CP_WAIT0();
            __syncthreads();
        }
    }

    const int gid = lane >> 2;
    const int cid = (lane & 3) * 2;
    #pragma unroll
    for (int mt = 0; mt < 4; mt++) {
        #pragma unroll
        for (int n8 = 0; n8 < 4; n8++) {
            int row = m0 + wm * 64 + mt * 16 + gid;
            int col = n0 + wn * 32 + n8 * 8 + cid;
            float b0 = __ldg(&bias[col]), b1 = __ldg(&bias[col + 1]);
            float2 v0 = make_float2(acc[mt][n8][0] + b0, acc[mt][n8][1] + b1);
            float2 v1 = make_float2(acc[mt][n8][2] + b0, acc[mt][n8][3] + b1);
            if (MODE == 0) {
                int h = col >> 6, d = col & 63;
                #pragma unroll
                for (int rr = 0; rr < 2; rr++) {
                    int r = row + rr * 8;
                    float2 v = rr ? v1 : v0;
                    int bi = r >> 10, ni = r & 1023;
                    size_t idx = (size_t)(((bi * NH + h) << 10) + ni) * 64 + d;
                    float e0, e1;
                    uint32_t hi = pack_bf16_res(v.x, v.y, e0, e1);
                    uint32_t lo = pack_bf16(e0, e1);
                    *(uint32_t*)&ohi[idx] = hi;
                    *(uint32_t*)&olo[idx] = lo;
                }
            } else {
                *(float2*)&out[(size_t)row * 512 + col]       = v0;
                *(float2*)&out[(size_t)(row + 8) * 512 + col] = v1;
            }
        }
    }
}

// fused QKV projection: blockIdx.z selects (X, W planes, bias, dst)
__global__ __launch_bounds__(256, 2) void gemm_qkv(
    const float* xq, const float* xk, const float* xv,
    const __nv_bfloat16* whi, const __nv_bfloat16* wlo,
    const float* bq, const float* bk, const float* bv,
    __nv_bfloat16* qh, __nv_bfloat16* ql,
    __nv_bfloat16* kh, __nv_bfloat16* kl,
    __nv_bfloat16* vh, __nv_bfloat16* vl)
{
    extern __shared__ char smem[];
    const int z = blockIdx.z;
    const float* X = (z == 0) ? xq : (z == 1) ? xk : xv;
    const float* B = (z == 0) ? bq : (z == 1) ? bk : bv;
    __nv_bfloat16* oh = (z == 0) ? qh : (z == 1) ? kh : vh;
    __nv_bfloat16* ol = (z == 0) ? ql : (z == 1) ? kl : vl;
    gemm_body<0>(X, whi + (size_t)z * WMAT, wlo + (size_t)z * WMAT,
                 B, nullptr, oh, ol, smem);
}

__global__ __launch_bounds__(256, 2) void gemm_out(
    const float* __restrict__ X,
    const __nv_bfloat16* __restrict__ whi, const __nv_bfloat16* __restrict__ wlo,
    const float* __restrict__ bias, float* __restrict__ out)
{
    extern __shared__ char smem[];
    gemm_body<1>(X, whi + (size_t)3 * WMAT, wlo + (size_t)3 * WMAT,
                 bias, out, nullptr, nullptr, smem);
}

// =============================================================================
// Register-resident fused attention (unchanged from R9 — known good):
// triple-buffered 16-chunk pipeline, 512 threads / 16 warps, 32 q-rows/CTA.
// =============================================================================
#define KVSTR   144
#define ATT_KVSZ 36864
#define ATT_LO   18432
#define ATT_Q    (3*ATT_KVSZ)
#define ATT_QLO  4608
#define ATT_W    (ATT_Q + 9216)
#define WSTR     132
#define ATT_WSZ  (32*WSTR*4)
#define ATT_PM   (ATT_W + 3*ATT_WSZ)
#define ATT_PS   (ATT_PM + 1024)
#define ATT_SMEM (ATT_PS + 1024)

__global__ __launch_bounds__(512, 1) void attn_tc(
    const __nv_bfloat16* __restrict__ qhi, const __nv_bfloat16* __restrict__ qlo,
    const __nv_bfloat16* __restrict__ khi, const __nv_bfloat16* __restrict__ klo,
    const __nv_bfloat16* __restrict__ vhi, const __nv_bfloat16* __restrict__ vlo,
    const float* __restrict__ gw, float* __restrict__ mn,
    float* __restrict__ attnout)
{
    extern __shared__ char smem[];
    const uint32_t sb = smem_u32(smem);
    float* pmaxs = (float*)(smem + ATT_PM);
    float* psums = (float*)(smem + ATT_PS);

    const int tid = threadIdx.x, wid = tid >> 5, lane = tid & 31;
    const int wmq = wid >> 3;
    const int wq  = wid & 7;
    const int q0 = blockIdx.x * 32, hh = blockIdx.y, bb = blockIdx.z;
    const size_t bhBase = (size_t)(bb * NH + hh) * NSEQ;

    auto loadChunk = [&](const __nv_bfloat16* hi, const __nv_bfloat16* lo,
                         int kb, int buf) {
        uint32_t dst = sb + buf * ATT_KVSZ;
        const __nv_bfloat16* sh = hi + (bhBase + kb * 128) * 64;
        const __nv_bfloat16* sl = lo + (bhBase + kb * 128) * 64;
        #pragma unroll
        for (int i = 0; i < 2; i++) {
            int idx = i * 512 + tid;
            int row = idx >> 3, col = (idx & 7) * 8;
            uint32_t d = dst + row * KVSTR + col * 2;
            cp16(d,          sh + row * 64 + col);
            cp16(d + ATT_LO, sl + row * 64 + col);
        }
    };
    auto loadW = [&](int kb, int buf) {
        uint32_t dst = sb + ATT_W + buf * ATT_WSZ;
        const float* src = gw + ((bhBase + q0) << 10) + kb * 128;
        #pragma unroll
        for (int i = 0; i < 2; i++) {
            int idx = i * 512 + tid;
            int row = idx >> 5, col = (idx & 31) * 4;
            cp16(dst + (uint32_t)(row * WSTR + col) * 4,
                 src + ((size_t)row << 10) + col);
        }
    };

    loadChunk(khi, klo, 0, 0);
    loadW(0, 0);
    CP_COMMIT();
    loadChunk(khi, klo, 1, 1);
    loadW(1, 1);
    CP_COMMIT();

    {
        int pos = tid & 255;
        int row = pos >> 3, col = (pos & 7) * 8;
        size_t g = (bhBase + q0 + row) * 64 + col;
        if (tid < 256)
            *(uint4*)(smem + ATT_Q + row * KVSTR + col * 2)           = *(const uint4*)&qhi[g];
        else
            *(uint4*)(smem + ATT_Q + ATT_QLO + row * KVSTR + col * 2) = *(const uint4*)&qlo[g];
    }
    __syncthreads();

    uint32_t aQh[4][4], aQl[4][4];
    {
        const uint32_t qaddr = sb + ATT_Q +
            ((uint32_t)((wmq * 16 + (lane & 15)) * 72) + (lane >> 4) * 8) * 2;
        #pragma unroll
        for (int ks = 0; ks < 4; ks++) {
            ldsm_x4(aQh[ks], qaddr + ks * 32);
            ldsm_x4(aQl[ks], qaddr + ks * 32 + ATT_QLO);
        }
    }

    const int g   = lane >> 2;
    const int c2  = (lane & 3) * 2;
    const int rl0 = wmq * 16 + g;
    const size_t grow0 = (bhBase + q0 + rl0) << 10;

    float s[8][8];
    float m0 = -1e30f, m1 = -1e30f;
    for (int kb = 0; kb < 8; kb++) {
        CP_WAIT1();
        __syncthreads();
        {
            int nc = kb + 2;
            if (nc < 8) {
                loadChunk(khi, klo, nc, nc % 3);
                loadW(nc, nc % 3);
            } else {
                loadChunk(vhi, vlo, nc - 8, nc % 3);
            }
            CP_COMMIT();
        }

        const uint32_t baddr = sb + (kb % 3) * ATT_KVSZ +
            ((uint32_t)((wq * 16 + (lane & 15)) * 72) + (lane >> 4) * 8) * 2;

        float t0h[4] = {0,0,0,0}, t0l[4] = {0,0,0,0}, t0m[4] = {0,0,0,0};
        float t1h[4] = {0,0,0,0}, t1l[4] = {0,0,0,0}, t1m[4] = {0,0,0,0};
        #pragma unroll
        for (int ks = 0; ks < 4; ks++) {
            uint32_t bh[4], bl[4];
            ldsm_x4(bh, baddr + ks * 32);
            ldsm_x4(bl, baddr + ks * 32 + ATT_LO);
            mma_bf16(t0h, aQh[ks], bh[0], bh[2]);
            mma_bf16(t0l, aQh[ks], bl[0], bl[2]);
            mma_bf16(t0m, aQl[ks], bh[0], bh[2]);
            mma_bf16(t1h, aQh[ks], bh[1], bh[3]);
            mma_bf16(t1l, aQh[ks], bl[1], bl[3]);
            mma_bf16(t1m, aQl[ks], bh[1], bh[3]);
        }

        const float* wsm = (const float*)(smem + ATT_W + (kb % 3) * ATT_WSZ);
        #pragma unroll
        for (int nt = 0; nt < 2; nt++) {
            int wcol = wq * 16 + nt * 8 + c2;
            float2 wa = *(const float2*)&wsm[rl0 * WSTR + wcol];
            float2 wb = *(const float2*)&wsm[(rl0 + 8) * WSTR + wcol];
            int j = nt * 4;
            float* ta = nt ? t1h : t0h;
            float* tb = nt ? t1l : t0l;
            float* tc = nt ? t1m : t0m;
            float v0 = (ta[0] + tb[0] + tc[0]) * 0.125f + __logf(fmaxf(wa.x, 1e-6f));
            float v1 = (ta[1] + tb[1] + tc[1]) * 0.125f + __logf(fmaxf(wa.y, 1e-6f));
            float v2 = (ta[2] + tb[2] + tc[2]) * 0.125f + __logf(fmaxf(wb.x, 1e-6f));
            float v3 = (ta[3] + tb[3] + tc[3]) * 0.125f + __logf(fmaxf(wb.y, 1e-6f));
            s[kb][j + 0] = v0; s[kb][j + 1] = v1;
            s[kb][j + 2] = v2; s[kb][j + 3] = v3;
            m0 = fmaxf(m0, fmaxf(v0, v1));
            m1 = fmaxf(m1, fmaxf(v2, v3));
        }
    }

    m0 = fmaxf(m0, __shfl_xor_sync(0xffffffffu, m0, 1));
    m0 = fmaxf(m0, __shfl_xor_sync(0xffffffffu, m0, 2));
    m1 = fmaxf(m1, __shfl_xor_sync(0xffffffffu, m1, 1));
    m1 = fmaxf(m1, __shfl_xor_sync(0xffffffffu, m1, 2));
    if ((lane & 3) == 0) {
        pmaxs[rl0 * 8 + wq]       = m0;
        pmaxs[(rl0 + 8) * 8 + wq] = m1;
    }
    __syncthreads();
    {
        float fm0 = -1e30f, fm1 = -1e30f;
        #pragma unroll
        for (int i = 0; i < 8; i++) {
            fm0 = fmaxf(fm0, pmaxs[rl0 * 8 + i]);
            fm1 = fmaxf(fm1, pmaxs[(rl0 + 8) * 8 + i]);
        }
        m0 = fm0; m1 = fm1;
    }
    float sum0 = 0.f, sum1 = 0.f;
    #pragma unroll
    for (int kb = 0; kb < 8; kb++) {
        #pragma unroll
        for (int j = 0; j < 8; j++) {
            float e = __expf(s[kb][j] - ((j & 2) ? m1 : m0));
            s[kb][j] = e;
            if (j & 2) sum1 += e; else sum0 += e;
        }
    }
    sum0 += __shfl_xor_sync(0xffffffffu, sum0, 1);
    sum0 += __shfl_xor_sync(0xffffffffu, sum0, 2);
    sum1 += __shfl_xor_sync(0xffffffffu, sum1, 1);
    sum1 += __shfl_xor_sync(0xffffffffu, sum1, 2);
    if ((lane & 3) == 0) {
        psums[rl0 * 8 + wq]       = sum0;
        psums[(rl0 + 8) * 8 + wq] = sum1;
    }
    __syncthreads();
    float inv0, inv1;
    {
        float t0 = 0.f, t1 = 0.f;
        #pragma unroll
        for (int i = 0; i < 8; i++) {
            t0 += psums[rl0 * 8 + i];
            t1 += psums[(rl0 + 8) * 8 + i];
        }
        inv0 = 1.f / t0; inv1 = 1.f / t1;
    }

    float* mrow0 = mn + grow0;
    float* mrow1 = mn + grow0 + (8 << 10);
    float accO[8][4];
    #pragma unroll
    for (int t = 0; t < 8; t++)
        #pragma unroll
        for (int j = 0; j < 4; j++) accO[t][j] = 0.f;

    for (int kb = 0; kb < 8; kb++) {
        const int c = kb + 8;
        CP_WAIT1();
        __syncthreads();
        {
            int nc = c + 2;
            if (nc < 16) loadChunk(vhi, vlo, nc - 8, nc % 3);
            CP_COMMIT();
        }

        #pragma unroll
        for (int nt = 0; nt < 2; nt++) {
            int col = kb * 128 + wq * 16 + nt * 8 + c2;
            int j = nt * 4;
            float p0 = s[kb][j + 0] * inv0;
            float p1 = s[kb][j + 1] * inv0;
            float p2 = s[kb][j + 2] * inv1;
            float p3 = s[kb][j + 3] * inv1;
            *(float2*)&mrow0[col] = make_float2(p0, p1);
            *(float2*)&mrow1[col] = make_float2(p2, p3);
            s[kb][j + 0] = __uint_as_float(packP(p0));
            s[kb][j + 1] = __uint_as_float(packP(p1));
            s[kb][j + 2] = __uint_as_float(packP(p2));
            s[kb][j + 3] = __uint_as_float(packP(p3));
        }

        uint32_t ah[4], al[4];
        {
            uint32_t w0 = __float_as_uint(s[kb][0]), w1 = __float_as_uint(s[kb][1]);
            uint32_t w2 = __float_as_uint(s[kb][2]), w3 = __float_as_uint(s[kb][3]);
            uint32_t w4 = __float_as_uint(s[kb][4]), w5 = __float_as_uint(s[kb][5]);
            uint32_t w6 = __float_as_uint(s[kb][6]), w7 = __float_as_uint(s[kb][7]);
            ah[0] = __byte_perm(w0, w1, 0x5410); al[0] = __byte_perm(w0, w1, 0x7632);
            ah[1] = __byte_perm(w2, w3, 0x5410); al[1] = __byte_perm(w2, w3, 0x7632);
            ah[2] = __byte_perm(w4, w5, 0x5410); al[2] = __byte_perm(w4, w5, 0x7632);
            ah[3] = __byte_perm(w6, w7, 0x5410); al[3] = __byte_perm(w6, w7, 0x7632);
        }

        const uint32_t vbase = sb + (c % 3) * ATT_KVSZ;
        #pragma unroll
        for (int ng = 0; ng < 4; ng++) {
            uint32_t vaddr = vbase +
                ((uint32_t)((wq * 16 + (lane & 15)) * 72) +
                 ng * 16 + (lane >> 4) * 8) * 2;
            uint32_t bh[4], bl[4];
            ldsm_x4t(bh, vaddr);
            ldsm_x4t(bl, vaddr + ATT_LO);
            float* c0 = accO[ng * 2];
            float* c1 = accO[ng * 2 + 1];
            mma_bf16(c0, ah, bh[0], bh[1]);
            mma_bf16(c0, ah, bl[0], bl[1]);
            mma_bf16(c0, al, bh[0], bh[1]);
            mma_bf16(c1, ah, bh[2], bh[3]);
            mma_bf16(c1, ah, bl[2], bl[3]);
            mma_bf16(c1, al, bh[2], bh[3]);
        }
    }
    __syncthreads();

    float* red = (float*)smem;
    {
        float* slab = red + wid * 1024;
        #pragma unroll
        for (int t = 0; t < 8; t++) {
            int col = (t >> 1) * 16 + (t & 1) * 8 + c2;
            *(float2*)&slab[g * 64 + col]       = make_float2(accO[t][0], accO[t][1]);
            *(float2*)&slab[(g + 8) * 64 + col] = make_float2(accO[t][2], accO[t][3]);
        }
    }
    __syncthreads();
    {
        int row = tid >> 4;
        int c4  = (tid & 15) * 4;
        int h   = row >> 4, rl = row & 15;
        float4 v = make_float4(0.f, 0.f, 0.f, 0.f);
        #pragma unroll
        for (int w2 = 0; w2 < 8; w2++) {
            float4 p = *(float4*)&red[(h * 8 + w2) * 1024 + rl * 64 + c4];
            v.x += p.x; v.y += p.y; v.z += p.z; v.w += p.w;
        }
        float* dst = attnout + (size_t)(bb * NSEQ + q0 + row) * 512 + hh * 64 + c4;
        *(float4*)dst = v;
    }
}

// =============================================================================
extern "C" void kernel_launch(void* const* d_in, const int* in_sizes, int n_in,
                              void* d_out, int out_size)
{
    const float* queries = (const float*)d_in[0];
    const float* keys    = (const float*)d_in[1];
    const float* values  = (const float*)d_in[2];
    const float* relw    = (const float*)d_in[3];
    const float* Wq = (const float*)d_in[4];
    const float* bq = (const float*)d_in[5];
    const float* Wk = (const float*)d_in[6];
    const float* bk = (const float*)d_in[7];
    const float* Wv = (const float*)d_in[8];
    const float* bv = (const float*)d_in[9];
    const float* Wo = (const float*)d_in[10];
    const float* bo = (const float*)d_in[11];

    float* out_main = (float*)d_out;
    float* out_mn   = (float*)d_out + (size_t)BATCH * NSEQ * DM;

    __nv_bfloat16 *qhi, *qlo, *khi, *klo, *vhi, *vlo, *whi, *wlo;
    float* gattn;
    cudaGetSymbolAddress((void**)&qhi, g_qhi);
    cudaGetSymbolAddress((void**)&qlo, g_qlo);
    cudaGetSymbolAddress((void**)&khi, g_khi);
    cudaGetSymbolAddress((void**)&klo, g_klo);
    cudaGetSymbolAddress((void**)&vhi, g_vhi);
    cudaGetSymbolAddress((void**)&vlo, g_vlo);
    cudaGetSymbolAddress((void**)&whi, g_whi);
    cudaGetSymbolAddress((void**)&wlo, g_wlo);
    cudaGetSymbolAddress((void**)&gattn, g_attn);

    cudaFuncSetAttribute(gemm_qkv, cudaFuncAttributeMaxDynamicSharedMemorySize, GEMM_SMEM);
    cudaFuncSetAttribute(gemm_out, cudaFuncAttributeMaxDynamicSharedMemorySize, GEMM_SMEM);
    cudaFuncSetAttribute(attn_tc, cudaFuncAttributeMaxDynamicSharedMemorySize, ATT_SMEM);

    conv_w<<<dim3(256, 4), 256>>>(Wq, Wk, Wv, Wo, whi, wlo);

    gemm_qkv<<<dim3(4, 128, 3), 256, GEMM_SMEM>>>(
        queries, keys, values, whi, wlo, bq, bk, bv,
        qhi, qlo, khi, klo, vhi, vlo);

    attn_tc<<<dim3(32, NH, BATCH), 512, ATT_SMEM>>>(
        qhi, qlo, khi, klo, vhi, vlo, relw, out_mn, gattn);

    gemm_out<<<dim3(4, 128), 256, GEMM_SMEM>>>(gattn, whi, wlo, bo, out_main);
}

// round 11
// speedup vs baseline: 1.4875x; 1.0286x over previous
#include <cuda_runtime.h>
#include <cuda_bf16.h>
#include <cstdint>
#include <math.h>

#define BATCH 16
#define NSEQ  1024
#define NH    8
#define HD    64
#define DM    512

// ---------------- scratch (static device arrays; no allocation) ----------------
#define QKV_ELEMS (BATCH*NH*NSEQ*HD)
__device__ __nv_bfloat16 g_qhi[QKV_ELEMS];
__device__ __nv_bfloat16 g_qlo[QKV_ELEMS];
__device__ __nv_bfloat16 g_khi[QKV_ELEMS];
__device__ __nv_bfloat16 g_klo[QKV_ELEMS];
__device__ __nv_bfloat16 g_vhi[QKV_ELEMS];
__device__ __nv_bfloat16 g_vlo[QKV_ELEMS];
__device__ float g_attn[BATCH*NSEQ*DM];
#define WMAT (512*512)
__device__ __nv_bfloat16 g_whi[4*WMAT];   // Wq, Wk, Wv, Wo hi planes
__device__ __nv_bfloat16 g_wlo[4*WMAT];

// =============================================================================
// helpers
// =============================================================================
__device__ __forceinline__ uint32_t smem_u32(const void* p) {
    uint32_t a;
    asm("{ .reg .u64 t; cvta.to.shared.u64 t, %1; cvt.u32.u64 %0, t; }"
        : "=r"(a) : "l"(p));
    return a;
}
__device__ __forceinline__ void ldsm_x4(uint32_t* r, uint32_t addr) {
    asm volatile("ldmatrix.sync.aligned.m8n8.x4.shared.b16 {%0,%1,%2,%3}, [%4];"
        : "=r"(r[0]), "=r"(r[1]), "=r"(r[2]), "=r"(r[3]) : "r"(addr));
}
__device__ __forceinline__ void ldsm_x4t(uint32_t* r, uint32_t addr) {
    asm volatile("ldmatrix.sync.aligned.m8n8.x4.trans.shared.b16 {%0,%1,%2,%3}, [%4];"
        : "=r"(r[0]), "=r"(r[1]), "=r"(r[2]), "=r"(r[3]) : "r"(addr));
}
__device__ __forceinline__ void mma_bf16(float* c, const uint32_t* a,
                                         uint32_t b0, uint32_t b1) {
    asm volatile(
        "mma.sync.aligned.m16n8k16.row.col.f32.bf16.bf16.f32 "
        "{%0,%1,%2,%3}, {%4,%5,%6,%7}, {%8,%9}, {%0,%1,%2,%3};"
        : "+f"(c[0]), "+f"(c[1]), "+f"(c[2]), "+f"(c[3])
        : "r"(a[0]), "r"(a[1]), "r"(a[2]), "r"(a[3]), "r"(b0), "r"(b1));
}
__device__ __forceinline__ void cp16(uint32_t dst, const void* src) {
    asm volatile("cp.async.cg.shared.global [%0], [%1], 16;" :: "r"(dst), "l"(src));
}
#define CP_COMMIT() asm volatile("cp.async.commit_group;" ::: "memory")
#define CP_WAIT0()  asm volatile("cp.async.wait_group 0;" ::: "memory")
#define CP_WAIT1()  asm volatile("cp.async.wait_group 1;" ::: "memory")

__device__ __forceinline__ uint32_t pack_bf16_res(float a, float b, float& ra, float& rb) {
    __nv_bfloat16 ha = __float2bfloat16(a), hb = __float2bfloat16(b);
    ra = a - __bfloat162float(ha);
    rb = b - __bfloat162float(hb);
    __nv_bfloat162 p(ha, hb);
    return *reinterpret_cast<uint32_t*>(&p);
}
__device__ __forceinline__ uint32_t pack_bf16(float a, float b) {
    __nv_bfloat162 p(__float2bfloat16(a), __float2bfloat16(b));
    return *reinterpret_cast<uint32_t*>(&p);
}
// word: low16 = bf16 hi(p), high16 = bf16 lo-residual(p)
__device__ __forceinline__ uint32_t packP(float p) {
    __nv_bfloat16 hi = __float2bfloat16(p);
    __nv_bfloat16 lo = __float2bfloat16(p - __bfloat162float(hi));
    uint16_t hb = *reinterpret_cast<uint16_t*>(&hi);
    uint16_t lb = *reinterpret_cast<uint16_t*>(&lo);
    return (uint32_t)hb | ((uint32_t)lb << 16);
}

// =============================================================================
// Weight pre-conversion: fp32 [512,512] -> bf16 hi/lo planes (once, all 4 mats)
// =============================================================================
__global__ __launch_bounds__(256) void conv_w(
    const float* w0, const float* w1, const float* w2, const float* w3,
    __nv_bfloat16* hi, __nv_bfloat16* lo)
{
    const int m = blockIdx.y;
    const float* w = (m == 0) ? w0 : (m == 1) ? w1 : (m == 2) ? w2 : w3;
    int idx = (blockIdx.x * 256 + threadIdx.x) * 4;
    float4 f = *(const float4*)&w[idx];
    float r0, r1, r2, r3;
    uint2 h, l;
    h.x = pack_bf16_res(f.x, f.y, r0, r1);
    h.y = pack_bf16_res(f.z, f.w, r2, r3);
    l.x = pack_bf16(r0, r1);
    l.y = pack_bf16(r2, r3);
    *(uint2*)&hi[m * WMAT + idx] = h;
    *(uint2*)&lo[m * WMAT + idx] = l;
}

// =============================================================================
// Tensor-core (HMMA) GEMM body: C[16384,512] = X @ W + bias, bf16 split-3.
// A: fp32 LDG -> convert -> STS (double-buffered via regs)
// B: pre-converted bf16 planes via cp.async (no convert, no reg staging)
// MODE 0: write bf16 hi/lo pair scattered to [b,h,n,d]. MODE 1: fp32 row-major.
// =============================================================================
#define ASTRIDE 40
#define BSTRIDE 136
#define A_BYTES (128*ASTRIDE*2)        // 10240
#define B_PLANE (32*BSTRIDE*2)         // 8704
#define OFF_ALO A_BYTES
#define OFF_BHI (2*A_BYTES)            // 20480
#define OFF_BLO (OFF_BHI + B_PLANE)    // 29184
#define GBUF    (OFF_BHI + 2*B_PLANE)  // 37888
#define GEMM_SMEM (2*GBUF)             // 75776

template<int MODE>
__device__ __forceinline__ void gemm_body(
    const float* __restrict__ X,
    const __nv_bfloat16* __restrict__ Whi, const __nv_bfloat16* __restrict__ Wlo,
    const float* __restrict__ bias, float* __restrict__ out,
    __nv_bfloat16* __restrict__ ohi, __nv_bfloat16* __restrict__ olo,
    char* smem)
{
    const uint32_t sb = smem_u32(smem);
    const int tid  = threadIdx.x;
    const int wid  = tid >> 5, lane = tid & 31;
    const int wm   = wid >> 2;
    const int wn   = wid & 3;
    const int n0   = blockIdx.x * 128;
    const int m0   = blockIdx.y * 128;

    float acc[4][4][4];
    #pragma unroll
    for (int i = 0; i < 4; i++)
        #pragma unroll
        for (int j = 0; j < 4; j++)
            #pragma unroll
            for (int k = 0; k < 4; k++) acc[i][j][k] = 0.f;

    float4 ra[4];

    auto gload = [&](int c) {
        const int k0 = c * 32;
        #pragma unroll
        for (int i = 0; i < 4; i++) {
            int idx = i * 256 + tid;
            int row = idx >> 3, col = (idx & 7) * 4;
            ra[i] = *(const float4*)&X[(size_t)(m0 + row) * 512 + k0 + col];
        }
    };

    auto bload = [&](int c, int buf) {
        const int k0 = c * 32;
        uint32_t dst = sb + buf * GBUF + OFF_BHI;
        const __nv_bfloat16* sh = Whi + (size_t)k0 * 512 + n0;
        const __nv_bfloat16* sl = Wlo + (size_t)k0 * 512 + n0;
        #pragma unroll
        for (int i = 0; i < 2; i++) {
            int idx = i * 256 + tid;
            int row = idx >> 4, col8 = (idx & 15) * 8;
            uint32_t d = dst + (uint32_t)(row * BSTRIDE + col8) * 2;
            cp16(d,               sh + row * 512 + col8);
            cp16(d + B_PLANE,     sl + row * 512 + col8);
        }
    };

    auto cstore = [&](int buf) {
        char* bp = smem + buf * GBUF;
        #pragma unroll
        for (int i = 0; i < 4; i++) {
            int idx = i * 256 + tid;
            int row = idx >> 3, col = (idx & 7) * 4;
            float r0, r1, r2, r3;
            uint2 hi, lo;
            hi.x = pack_bf16_res(ra[i].x, ra[i].y, r0, r1);
            hi.y = pack_bf16_res(ra[i].z, ra[i].w, r2, r3);
            lo.x = pack_bf16(r0, r1);
            lo.y = pack_bf16(r2, r3);
            uint32_t off = (uint32_t)(row * ASTRIDE + col) * 2;
            *(uint2*)(bp + off)           = hi;
            *(uint2*)(bp + OFF_ALO + off) = lo;
        }
    };

    const uint32_t aLane = (uint32_t)((wm * 64 + (lane & 15)) * ASTRIDE + (lane >> 4) * 8) * 2;
    const uint32_t bLane = (uint32_t)((lane & 15) * BSTRIDE + wn * 32 + (lane >> 4) * 8) * 2;

    auto compute = [&](int buf) {
        const uint32_t base = sb + buf * GBUF;
        #pragma unroll
        for (int ks = 0; ks < 2; ks++) {
            uint32_t ah[4][4], al[4][4], bh[2][4], bl[2][4];
            #pragma unroll
            for (int mt = 0; mt < 4; mt++) {
                uint32_t ad = base + aLane + (uint32_t)(mt * 16 * ASTRIDE + ks * 16) * 2;
                ldsm_x4(ah[mt], ad);
                ldsm_x4(al[mt], ad + OFF_ALO);
            }
            #pragma unroll
            for (int nt = 0; nt < 2; nt++) {
                uint32_t bd = base + OFF_BHI + bLane +
                              (uint32_t)(ks * 16 * BSTRIDE + nt * 16) * 2;
                ldsm_x4t(bh[nt], bd);
                ldsm_x4t(bl[nt], bd + B_PLANE);
            }
            #pragma unroll
            for (int mt = 0; mt < 4; mt++) {
                #pragma unroll
                for (int n8 = 0; n8 < 4; n8++) {
                    const int nt = n8 >> 1, hf = (n8 & 1) * 2;
                    float* c = acc[mt][n8];
                    mma_bf16(c, ah[mt], bh[nt][hf], bh[nt][hf + 1]);
                    mma_bf16(c, ah[mt], bl[nt][hf], bl[nt][hf + 1]);
                    mma_bf16(c, al[mt], bh[nt][hf], bh[nt][hf + 1]);
                }
            }
        }
    };

    gload(0);
    bload(0, 0);
    CP_COMMIT();
    cstore(0);
    CP_WAIT0();
    __syncthreads();
    for (int c = 0; c < 16; c++) {
        if (c < 15) {
            bload(c + 1, (c + 1) & 1);
            CP_COMMIT();
            gload(c + 1);
        }
        compute(c & 1);
        if (c < 15) {
            cstore((c + 1) & 1);
            CP_WAIT0();
            __syncthreads();
        }
    }

    const int gid = lane >> 2;
    const int cid = (lane & 3) * 2;
    #pragma unroll
    for (int mt = 0; mt < 4; mt++) {
        #pragma unroll
        for (int n8 = 0; n8 < 4; n8++) {
            int row = m0 + wm * 64 + mt * 16 + gid;
            int col = n0 + wn * 32 + n8 * 8 + cid;
            float b0 = __ldg(&bias[col]), b1 = __ldg(&bias[col + 1]);
            float2 v0 = make_float2(acc[mt][n8][0] + b0, acc[mt][n8][1] + b1);
            float2 v1 = make_float2(acc[mt][n8][2] + b0, acc[mt][n8][3] + b1);
            if (MODE == 0) {
                int h = col >> 6, d = col & 63;
                #pragma unroll
                for (int rr = 0; rr < 2; rr++) {
                    int r = row + rr * 8;
                    float2 v = rr ? v1 : v0;
                    int bi = r >> 10, ni = r & 1023;
                    size_t idx = (size_t)(((bi * NH + h) << 10) + ni) * 64 + d;
                    float e0, e1;
                    uint32_t hi = pack_bf16_res(v.x, v.y, e0, e1);
                    uint32_t lo = pack_bf16(e0, e1);
                    *(uint32_t*)&ohi[idx] = hi;
                    *(uint32_t*)&olo[idx] = lo;
                }
            } else {
                *(float2*)&out[(size_t)row * 512 + col]       = v0;
                *(float2*)&out[(size_t)(row + 8) * 512 + col] = v1;
            }
        }
    }
}

// fused QKV projection: blockIdx.z selects (X, W planes, bias, dst)
__global__ __launch_bounds__(256, 2) void gemm_qkv(
    const float* xq, const float* xk, const float* xv,
    const __nv_bfloat16* whi, const __nv_bfloat16* wlo,
    const float* bq, const float* bk, const float* bv,
    __nv_bfloat16* qh, __nv_bfloat16* ql,
    __nv_bfloat16* kh, __nv_bfloat16* kl,
    __nv_bfloat16* vh, __nv_bfloat16* vl)
{
    extern __shared__ char smem[];
    const int z = blockIdx.z;
    const float* X = (z == 0) ? xq : (z == 1) ? xk : xv;
    const float* B = (z == 0) ? bq : (z == 1) ? bk : bv;
    __nv_bfloat16* oh = (z == 0) ? qh : (z == 1) ? kh : vh;
    __nv_bfloat16* ol = (z == 0) ? ql : (z == 1) ? kl : vl;
    gemm_body<0>(X, whi + (size_t)z * WMAT, wlo + (size_t)z * WMAT,
                 B, nullptr, oh, ol, smem);
}

__global__ __launch_bounds__(256, 2) void gemm_out(
    const float* __restrict__ X,
    const __nv_bfloat16* __restrict__ whi, const __nv_bfloat16* __restrict__ wlo,
    const float* __restrict__ bias, float* __restrict__ out)
{
    extern __shared__ char smem[];
    gemm_body<1>(X, whi + (size_t)3 * WMAT, wlo + (size_t)3 * WMAT,
                 bias, out, nullptr, nullptr, smem);
}

// =============================================================================
// Register-resident fused attention, triple-buffered 16-chunk pipeline.
// Softmax identity: softmax(log(clip(w)) + a) = clip(w)*exp(a) / sum(...)
//   -> no log (MUFU halved), no max pass (|a| <~ 7, fp32-safe), exp fused
//      into the QK merge with running sums.
// 512 threads / 16 warps, 32 q-rows/CTA.
// =============================================================================
#define KVSTR   144
#define ATT_KVSZ 36864
#define ATT_LO   18432
#define ATT_Q    (3*ATT_KVSZ)
#define ATT_QLO  4608
#define ATT_W    (ATT_Q + 9216)
#define WSTR     132
#define ATT_WSZ  (32*WSTR*4)
#define ATT_PS   (ATT_W + 3*ATT_WSZ)
#define ATT_SMEM (ATT_PS + 1024)

__global__ __launch_bounds__(512, 1) void attn_tc(
    const __nv_bfloat16* __restrict__ qhi, const __nv_bfloat16* __restrict__ qlo,
    const __nv_bfloat16* __restrict__ khi, const __nv_bfloat16* __restrict__ klo,
    const __nv_bfloat16* __restrict__ vhi, const __nv_bfloat16* __restrict__ vlo,
    const float* __restrict__ gw, float* __restrict__ mn,
    float* __restrict__ attnout)
{
    extern __shared__ char smem[];
    const uint32_t sb = smem_u32(smem);
    float* psums = (float*)(smem + ATT_PS);

    const int tid = threadIdx.x, wid = tid >> 5, lane = tid & 31;
    const int wmq = wid >> 3;
    const int wq  = wid & 7;
    const int q0 = blockIdx.x * 32, hh = blockIdx.y, bb = blockIdx.z;
    const size_t bhBase = (size_t)(bb * NH + hh) * NSEQ;
    const float EXC = 0.18033688011112042f;   // 0.125 * log2(e)

    auto loadChunk = [&](const __nv_bfloat16* hi, const __nv_bfloat16* lo,
                         int kb, int buf) {
        uint32_t dst = sb + buf * ATT_KVSZ;
        const __nv_bfloat16* sh = hi + (bhBase + kb * 128) * 64;
        const __nv_bfloat16* sl = lo + (bhBase + kb * 128) * 64;
        #pragma unroll
        for (int i = 0; i < 2; i++) {
            int idx = i * 512 + tid;
            int row = idx >> 3, col = (idx & 7) * 8;
            uint32_t d = dst + row * KVSTR + col * 2;
            cp16(d,          sh + row * 64 + col);
            cp16(d + ATT_LO, sl + row * 64 + col);
        }
    };
    auto loadW = [&](int kb, int buf) {
        uint32_t dst = sb + ATT_W + buf * ATT_WSZ;
        const float* src = gw + ((bhBase + q0) << 10) + kb * 128;
        #pragma unroll
        for (int i = 0; i < 2; i++) {
            int idx = i * 512 + tid;
            int row = idx >> 5, col = (idx & 31) * 4;
            cp16(dst + (uint32_t)(row * WSTR + col) * 4,
                 src + ((size_t)row << 10) + col);
        }
    };

    loadChunk(khi, klo, 0, 0);
    loadW(0, 0);
    CP_COMMIT();
    loadChunk(khi, klo, 1, 1);
    loadW(1, 1);
    CP_COMMIT();

    {
        int pos = tid & 255;
        int row = pos >> 3, col = (pos & 7) * 8;
        size_t g = (bhBase + q0 + row) * 64 + col;
        if (tid < 256)
            *(uint4*)(smem + ATT_Q + row * KVSTR + col * 2)           = *(const uint4*)&qhi[g];
        else
            *(uint4*)(smem + ATT_Q + ATT_QLO + row * KVSTR + col * 2) = *(const uint4*)&qlo[g];
    }
    __syncthreads();

    uint32_t aQh[4][4], aQl[4][4];
    {
        const uint32_t qaddr = sb + ATT_Q +
            ((uint32_t)((wmq * 16 + (lane & 15)) * 72) + (lane >> 4) * 8) * 2;
        #pragma unroll
        for (int ks = 0; ks < 4; ks++) {
            ldsm_x4(aQh[ks], qaddr + ks * 32);
            ldsm_x4(aQl[ks], qaddr + ks * 32 + ATT_QLO);
        }
    }

    const int g   = lane >> 2;
    const int c2  = (lane & 3) * 2;
    const int rl0 = wmq * 16 + g;
    const size_t grow0 = (bhBase + q0 + rl0) << 10;

    // ========== QK^T + fused w*exp(score/8) + running sums ==========
    float s[8][8];
    float sum0 = 0.f, sum1 = 0.f;
    for (int kb = 0; kb < 8; kb++) {
        CP_WAIT1();
        __syncthreads();
        {
            int nc = kb + 2;
            if (nc < 8) {
                loadChunk(khi, klo, nc, nc % 3);
                loadW(nc, nc % 3);
            } else {
                loadChunk(vhi, vlo, nc - 8, nc % 3);
            }
            CP_COMMIT();
        }

        const uint32_t baddr = sb + (kb % 3) * ATT_KVSZ +
            ((uint32_t)((wq * 16 + (lane & 15)) * 72) + (lane >> 4) * 8) * 2;

        float t0h[4] = {0,0,0,0}, t0l[4] = {0,0,0,0}, t0m[4] = {0,0,0,0};
        float t1h[4] = {0,0,0,0}, t1l[4] = {0,0,0,0}, t1m[4] = {0,0,0,0};
        #pragma unroll
        for (int ks = 0; ks < 4; ks++) {
            uint32_t bh[4], bl[4];
            ldsm_x4(bh, baddr + ks * 32);
            ldsm_x4(bl, baddr + ks * 32 + ATT_LO);
            mma_bf16(t0h, aQh[ks], bh[0], bh[2]);
            mma_bf16(t0l, aQh[ks], bl[0], bl[2]);
            mma_bf16(t0m, aQl[ks], bh[0], bh[2]);
            mma_bf16(t1h, aQh[ks], bh[1], bh[3]);
            mma_bf16(t1l, aQh[ks], bl[1], bl[3]);
            mma_bf16(t1m, aQl[ks], bh[1], bh[3]);
        }

        const float* wsm = (const float*)(smem + ATT_W + (kb % 3) * ATT_WSZ);
        #pragma unroll
        for (int nt = 0; nt < 2; nt++) {
            int wcol = wq * 16 + nt * 8 + c2;
            float2 wa = *(const float2*)&wsm[rl0 * WSTR + wcol];
            float2 wb = *(const float2*)&wsm[(rl0 + 8) * WSTR + wcol];
            int j = nt * 4;
            float* ta = nt ? t1h : t0h;
            float* tb = nt ? t1l : t0l;
            float* tc = nt ? t1m : t0m;
            float e0 = fmaxf(wa.x, 1e-6f) * exp2f((ta[0] + tb[0] + tc[0]) * EXC);
            float e1 = fmaxf(wa.y, 1e-6f) * exp2f((ta[1] + tb[1] + tc[1]) * EXC);
            float e2 = fmaxf(wb.x, 1e-6f) * exp2f((ta[2] + tb[2] + tc[2]) * EXC);
            float e3 = fmaxf(wb.y, 1e-6f) * exp2f((ta[3] + tb[3] + tc[3]) * EXC);
            s[kb][j + 0] = e0; s[kb][j + 1] = e1;
            s[kb][j + 2] = e2; s[kb][j + 3] = e3;
            sum0 += e0 + e1;
            sum1 += e2 + e3;
        }
    }

    // ========== sum reduction (V0/V1 landing meanwhile) ==========
    sum0 += __shfl_xor_sync(0xffffffffu, sum0, 1);
    sum0 += __shfl_xor_sync(0xffffffffu, sum0, 2);
    sum1 += __shfl_xor_sync(0xffffffffu, sum1, 1);
    sum1 += __shfl_xor_sync(0xffffffffu, sum1, 2);
    if ((lane & 3) == 0) {
        psums[rl0 * 8 + wq]       = sum0;
        psums[(rl0 + 8) * 8 + wq] = sum1;
    }
    __syncthreads();
    float inv0, inv1;
    {
        float t0 = 0.f, t1 = 0.f;
        #pragma unroll
        for (int i = 0; i < 8; i++) {
            t0 += psums[rl0 * 8 + i];
            t1 += psums[(rl0 + 8) * 8 + i];
        }
        inv0 = 1.f / t0; inv1 = 1.f / t1;
    }

    // ========== P @ V with fused normalize/pack/mn-store ==========
    float* mrow0 = mn + grow0;
    float* mrow1 = mn + grow0 + (8 << 10);
    float accO[8][4];
    #pragma unroll
    for (int t = 0; t < 8; t++)
        #pragma unroll
        for (int j = 0; j < 4; j++) accO[t][j] = 0.f;

    for (int kb = 0; kb < 8; kb++) {
        const int c = kb + 8;
        CP_WAIT1();
        __syncthreads();
        {
            int nc = c + 2;
            if (nc < 16) loadChunk(vhi, vlo, nc - 8, nc % 3);
            CP_COMMIT();
        }

        #pragma unroll
        for (int nt = 0; nt < 2; nt++) {
            int col = kb * 128 + wq * 16 + nt * 8 + c2;
            int j = nt * 4;
            float p0 = s[kb][j + 0] * inv0;
            float p1 = s[kb][j + 1] * inv0;
            float p2 = s[kb][j + 2] * inv1;
            float p3 = s[kb][j + 3] * inv1;
            *(float2*)&mrow0[col] = make_float2(p0, p1);
            *(float2*)&mrow1[col] = make_float2(p2, p3);
            s[kb][j + 0] = __uint_as_float(packP(p0));
            s[kb][j + 1] = __uint_as_float(packP(p1));
            s[kb][j + 2] = __uint_as_float(packP(p2));
            s[kb][j + 3] = __uint_as_float(packP(p3));
        }

        uint32_t ah[4], al[4];
        {
            uint32_t w0 = __float_as_uint(s[kb][0]), w1 = __float_as_uint(s[kb][1]);
            uint32_t w2 = __float_as_uint(s[kb][2]), w3 = __float_as_uint(s[kb][3]);
            uint32_t w4 = __float_as_uint(s[kb][4]), w5 = __float_as_uint(s[kb][5]);
            uint32_t w6 = __float_as_uint(s[kb][6]), w7 = __float_as_uint(s[kb][7]);
            ah[0] = __byte_perm(w0, w1, 0x5410); al[0] = __byte_perm(w0, w1, 0x7632);
            ah[1] = __byte_perm(w2, w3, 0x5410); al[1] = __byte_perm(w2, w3, 0x7632);
            ah[2] = __byte_perm(w4, w5, 0x5410); al[2] = __byte_perm(w4, w5, 0x7632);
            ah[3] = __byte_perm(w6, w7, 0x5410); al[3] = __byte_perm(w6, w7, 0x7632);
        }

        const uint32_t vbase = sb + (c % 3) * ATT_KVSZ;
        #pragma unroll
        for (int ng = 0; ng < 4; ng++) {
            uint32_t vaddr = vbase +
                ((uint32_t)((wq * 16 + (lane & 15)) * 72) +
                 ng * 16 + (lane >> 4) * 8) * 2;
            uint32_t bh[4], bl[4];
            ldsm_x4t(bh, vaddr);
            ldsm_x4t(bl, vaddr + ATT_LO);
            float* c0 = accO[ng * 2];
            float* c1 = accO[ng * 2 + 1];
            mma_bf16(c0, ah, bh[0], bh[1]);
            mma_bf16(c0, ah, bl[0], bl[1]);
            mma_bf16(c0, al, bh[0], bh[1]);
            mma_bf16(c1, ah, bh[2], bh[3]);
            mma_bf16(c1, ah, bl[2], bl[3]);
            mma_bf16(c1, al, bh[2], bh[3]);
        }
    }
    __syncthreads();

    float* red = (float*)smem;
    {
        float* slab = red + wid * 1024;
        #pragma unroll
        for (int t = 0; t < 8; t++) {
            int col = (t >> 1) * 16 + (t & 1) * 8 + c2;
            *(float2*)&slab[g * 64 + col]       = make_float2(accO[t][0], accO[t][1]);
            *(float2*)&slab[(g + 8) * 64 + col] = make_float2(accO[t][2], accO[t][3]);
        }
    }
    __syncthreads();
    {
        int row = tid >> 4;
        int c4  = (tid & 15) * 4;
        int h   = row >> 4, rl = row & 15;
        float4 v = make_float4(0.f, 0.f, 0.f, 0.f);
        #pragma unroll
        for (int w2 = 0; w2 < 8; w2++) {
            float4 p = *(float4*)&red[(h * 8 + w2) * 1024 + rl * 64 + c4];
            v.x += p.x; v.y += p.y; v.z += p.z; v.w += p.w;
        }
        float* dst = attnout + (size_t)(bb * NSEQ + q0 + row) * 512 + hh * 64 + c4;
        *(float4*)dst = v;
    }
}

// =============================================================================
extern "C" void kernel_launch(void* const* d_in, const int* in_sizes, int n_in,
                              void* d_out, int out_size)
{
    const float* queries = (const float*)d_in[0];
    const float* keys    = (const float*)d_in[1];
    const float* values  = (const float*)d_in[2];
    const float* relw    = (const float*)d_in[3];
    const float* Wq = (const float*)d_in[4];
    const float* bq = (const float*)d_in[5];
    const float* Wk = (const float*)d_in[6];
    const float* bk = (const float*)d_in[7];
    const float* Wv = (const float*)d_in[8];
    const float* bv = (const float*)d_in[9];
    const float* Wo = (const float*)d_in[10];
    const float* bo = (const float*)d_in[11];

    float* out_main = (float*)d_out;
    float* out_mn   = (float*)d_out + (size_t)BATCH * NSEQ * DM;

    __nv_bfloat16 *qhi, *qlo, *khi, *klo, *vhi, *vlo, *whi, *wlo;
    float* gattn;
    cudaGetSymbolAddress((void**)&qhi, g_qhi);
    cudaGetSymbolAddress((void**)&qlo, g_qlo);
    cudaGetSymbolAddress((void**)&khi, g_khi);
    cudaGetSymbolAddress((void**)&klo, g_klo);
    cudaGetSymbolAddress((void**)&vhi, g_vhi);
    cudaGetSymbolAddress((void**)&vlo, g_vlo);
    cudaGetSymbolAddress((void**)&whi, g_whi);
    cudaGetSymbolAddress((void**)&wlo, g_wlo);
    cudaGetSymbolAddress((void**)&gattn, g_attn);

    cudaFuncSetAttribute(gemm_qkv, cudaFuncAttributeMaxDynamicSharedMemorySize, GEMM_SMEM);
    cudaFuncSetAttribute(gemm_out, cudaFuncAttributeMaxDynamicSharedMemorySize, GEMM_SMEM);
    cudaFuncSetAttribute(attn_tc, cudaFuncAttributeMaxDynamicSharedMemorySize, ATT_SMEM);

    conv_w<<<dim3(256, 4), 256>>>(Wq, Wk, Wv, Wo, whi, wlo);

    gemm_qkv<<<dim3(4, 128, 3), 256, GEMM_SMEM>>>(
        queries, keys, values, whi, wlo, bq, bk, bv,
        qhi, qlo, khi, klo, vhi, vlo);

    attn_tc<<<dim3(32, NH, BATCH), 512, ATT_SMEM>>>(
        qhi, qlo, khi, klo, vhi, vlo, relw, out_mn, gattn);

    gemm_out<<<dim3(4, 128), 256, GEMM_SMEM>>>(gattn, whi, wlo, bo, out_main);
}